// round 8
// baseline (speedup 1.0000x reference)
#include <cuda_runtime.h>
#include <cstdint>
#include <cstddef>

// Problem constants
#define N_TOT 131072   // B*S points
#define D_DIM 256      // feature dim
#define K_CL  512      // clusters

#define MT 128         // points per CTA tile (R4 proven config)
#define TAU 0.4f       // tf32 near-tie threshold (err-diff RMS ~0.022 -> ~18 sigma)

// ---- dynamic SMEM layout (bytes) ----
// X tile: [128][260] f32 (tf32 bits, stride 260 -> conflict-free frag LDS)
#define XSTR 260
#define BSTR 68                        // C chunk row stride (64 dims + 4 pad)
#define SM_X   0                       // 133120 bytes
#define SM_B0  133120                  // C chunk buf0: [128][68] f32 = 34816
#define SM_B1  (SM_B0 + 34816)         // 167936
#define SM_C2  (SM_B1 + 34816)         // 202752: 512 f32
#define SM_BV  (SM_C2 + 2048)          // float[4][128]
#define SM_SV  (SM_BV + 2048)
#define SM_IV  (SM_SV + 2048)
#define SMEM_TOTAL (SM_IV + 2048)      // 210944

// Scratch (device globals — no allocation allowed)
__device__ int   g_idx[N_TOT];
__device__ int   g_rank[N_TOT];
__device__ int   g_order[N_TOT];
__device__ int   g_cnt2[K_CL];
__device__ int   g_off[K_CL];
__device__ float g_part[4][K_CL][D_DIM];   // gather partials (2 MB)
__device__ float g_c2[K_CL];
__device__ int   g_nref;
__device__ int   g_rlist[N_TOT];

// ---------------- portable PTX helpers (NO 'a'-gated features) -------------
__device__ __forceinline__ uint32_t f2tf(float f) {
    uint32_t r;
    asm("cvt.rna.tf32.f32 %0, %1;" : "=r"(r) : "f"(f));
    return r;
}
__device__ __forceinline__ void mma8(float* d, const uint32_t* a, const uint32_t* b) {
    asm volatile(
        "mma.sync.aligned.m16n8k8.row.col.f32.tf32.tf32.f32 "
        "{%0,%1,%2,%3}, {%4,%5,%6,%7}, {%8,%9}, {%0,%1,%2,%3};"
        : "+f"(d[0]), "+f"(d[1]), "+f"(d[2]), "+f"(d[3])
        : "r"(a[0]), "r"(a[1]), "r"(a[2]), "r"(a[3]), "r"(b[0]), "r"(b[1]));
}

// ---------------------------------------------------------------------------
// init: zero refine/rank counters, c2[k] = sum_d C[k][d]^2 (fp64->fp32)
// ---------------------------------------------------------------------------
__global__ void init_kernel(const float* __restrict__ C) {
    int t = blockIdx.x * blockDim.x + threadIdx.x;
    if (t == 0) g_nref = 0;
    if (t < K_CL) {
        g_cnt2[t] = 0;
        const float4* c = (const float4*)(C + (size_t)t * D_DIM);
        double s = 0.0;
        #pragma unroll
        for (int j = 0; j < D_DIM / 4; ++j) {
            float4 v = c[j];
            s += (double)v.x * v.x + (double)v.y * v.y
               + (double)v.z * v.z + (double)v.w * v.w;
        }
        g_c2[t] = (float)s;
    }
}

// pad kernels: place argmin_mma at the ncu-captured 4th launch slot
__global__ void pad_kernel() {}

// ---------------------------------------------------------------------------
// mma.sync tf32 fused distance-GEMM + top-2 argmin per 128-point tile.
// R4 structure (64x32 warp tiles, 2m x 4n grid, 16 chunks of 128clx64d),
// but ALL tf32 converts hoisted out of the inner loop:
//   X: LDG -> cvt -> STS once;  C: LDG(regs, double-buffer) -> cvt -> STS.
// Inner loop is pure LDS + HMMA. Streams full one-hot rows (no memset).
// ---------------------------------------------------------------------------
__global__ __launch_bounds__(256)
void argmin_mma(const float* __restrict__ X, const float* __restrict__ C,
                float* __restrict__ out) {
    extern __shared__ char smem[];
    const int tid  = threadIdx.x;
    const int wid  = tid >> 5, lane = tid & 31;
    const int qrow = lane >> 2, qcol = lane & 3;
    const int wm   = wid & 1,  wn   = wid >> 1;   // 2m x 4n warp grid
    const int RM   = wm * 64,  CN   = wn * 32;
    const int n0   = blockIdx.x * MT;

    float* Xs  = (float*)(smem + SM_X);
    float* Bb[2] = { (float*)(smem + SM_B0), (float*)(smem + SM_B1) };
    float* c2s = (float*)(smem + SM_C2);
    float* bvS = (float*)(smem + SM_BV);
    float* svS = (float*)(smem + SM_SV);
    int*   ivS = (int*)  (smem + SM_IV);

    // stage c2
    c2s[tid]       = g_c2[tid];
    c2s[tid + 256] = g_c2[tid + 256];

    // ---- C chunk path: LDG into regs -> cvt -> STS (double buffered) ----
    float4 pr[8];
    auto ldgB = [&](int q) {
        const int kt = (q >> 2) * 128, db = (q & 3) * 64;
        #pragma unroll
        for (int i = 0; i < 8; ++i) {
            int idx = i * 256 + tid;
            int r = idx >> 4, s = idx & 15;
            pr[i] = *(const float4*)(C + (size_t)(kt + r) * D_DIM + db + s * 4);
        }
    };
    auto stsB = [&](float* B) {
        #pragma unroll
        for (int i = 0; i < 8; ++i) {
            int idx = i * 256 + tid;
            int r = idx >> 4, s = idx & 15;
            float4 w;
            w.x = __uint_as_float(f2tf(pr[i].x));
            w.y = __uint_as_float(f2tf(pr[i].y));
            w.z = __uint_as_float(f2tf(pr[i].z));
            w.w = __uint_as_float(f2tf(pr[i].w));
            *(float4*)(B + r * BSTR + s * 4) = w;
        }
    };

    ldgB(0);

    // ---- X tile: LDG -> cvt -> STS (identical layout/indices to R4) ----
    #pragma unroll
    for (int i = 0; i < 32; ++i) {
        int idx = i * 256 + tid;
        int r = idx >> 6, s = idx & 63;
        float4 v = *(const float4*)(X + (size_t)(n0 + r) * D_DIM + s * 4);
        float4 w;
        w.x = __uint_as_float(f2tf(v.x));
        w.y = __uint_as_float(f2tf(v.y));
        w.z = __uint_as_float(f2tf(v.z));
        w.w = __uint_as_float(f2tf(v.w));
        *(float4*)(Xs + r * XSTR + s * 4) = w;
    }

    stsB(Bb[0]);          // publish chunk 0
    ldgB(1);              // chunk 1 in regs
    __syncthreads();      // X, B0, c2 visible

    float acc[4][4][4];
    #pragma unroll
    for (int a = 0; a < 4; ++a)
        #pragma unroll
        for (int b = 0; b < 4; ++b)
            #pragma unroll
            for (int c = 0; c < 4; ++c) acc[a][b][c] = 0.0f;

    float best[8], sec[8];
    int   idx8[8];
    #pragma unroll
    for (int t = 0; t < 8; ++t) { best[t] = 3.4e38f; sec[t] = 3.4e38f; idx8[t] = 0; }

    for (int q = 0; q < 16; ++q) {
        const float* Bs = Bb[q & 1];
        const int dbase = (q & 3) * 64;

        #pragma unroll
        for (int ks = 0; ks < 8; ++ks) {
            const int dX = dbase + ks * 8 + qcol;
            uint32_t Af[4][4];
            #pragma unroll
            for (int mt = 0; mt < 4; ++mt) {
                int r = RM + mt * 16 + qrow;
                Af[mt][0] = __float_as_uint(Xs[r * XSTR + dX]);
                Af[mt][1] = __float_as_uint(Xs[(r + 8) * XSTR + dX]);
                Af[mt][2] = __float_as_uint(Xs[r * XSTR + dX + 4]);
                Af[mt][3] = __float_as_uint(Xs[(r + 8) * XSTR + dX + 4]);
            }
            uint32_t Bf[4][2];
            #pragma unroll
            for (int nt = 0; nt < 4; ++nt) {
                int n = CN + nt * 8 + qrow;
                Bf[nt][0] = __float_as_uint(Bs[n * BSTR + ks * 8 + qcol]);
                Bf[nt][1] = __float_as_uint(Bs[n * BSTR + ks * 8 + 4 + qcol]);
            }
            #pragma unroll
            for (int mt = 0; mt < 4; ++mt)
                #pragma unroll
                for (int nt = 0; nt < 4; ++nt)
                    mma8(acc[mt][nt], Af[mt], Bf[nt]);
        }

        if ((q & 3) == 3) {
            // pass epilogue: score = c2 - 2*dot, per-slot top-2, zero acc
            const int kt = (q >> 2) * 128;
            #pragma unroll
            for (int mt = 0; mt < 4; ++mt) {
                #pragma unroll
                for (int nt = 0; nt < 4; ++nt) {
                    int k0 = kt + CN + nt * 8 + 2 * qcol;
                    float c20 = c2s[k0], c21 = c2s[k0 + 1];
                    float s0 = fmaf(-2.0f, acc[mt][nt][0], c20);
                    float s1 = fmaf(-2.0f, acc[mt][nt][1], c21);
                    float s2 = fmaf(-2.0f, acc[mt][nt][2], c20);
                    float s3 = fmaf(-2.0f, acc[mt][nt][3], c21);
                    int t0 = mt * 2, t1 = mt * 2 + 1;
                    if (s0 < sec[t0]) { if (s0 < best[t0]) { sec[t0] = best[t0]; best[t0] = s0; idx8[t0] = k0; } else sec[t0] = s0; }
                    if (s1 < sec[t0]) { if (s1 < best[t0]) { sec[t0] = best[t0]; best[t0] = s1; idx8[t0] = k0 + 1; } else sec[t0] = s1; }
                    if (s2 < sec[t1]) { if (s2 < best[t1]) { sec[t1] = best[t1]; best[t1] = s2; idx8[t1] = k0; } else sec[t1] = s2; }
                    if (s3 < sec[t1]) { if (s3 < best[t1]) { sec[t1] = best[t1]; best[t1] = s3; idx8[t1] = k0 + 1; } else sec[t1] = s3; }
                    acc[mt][nt][0] = 0.0f; acc[mt][nt][1] = 0.0f;
                    acc[mt][nt][2] = 0.0f; acc[mt][nt][3] = 0.0f;
                }
            }
        }

        __syncthreads();                   // all warps done reading buf (q+1)&1
        if (q + 1 < 16) stsB(Bb[(q + 1) & 1]);   // publish chunk q+1 (in regs)
        if (q + 2 < 16) ldgB(q + 2);             // fetch chunk q+2 into regs
        if (q + 1 < 16) __syncthreads();         // chunk q+1 visible
    }

    // quad merge (lanes differing in qcol share rows)
    #pragma unroll
    for (int t = 0; t < 8; ++t) {
        float b = best[t], s = sec[t];
        int   i = idx8[t];
        #pragma unroll
        for (int o = 1; o <= 2; o <<= 1) {
            float b2 = __shfl_xor_sync(0xFFFFFFFFu, b, o);
            float s2 = __shfl_xor_sync(0xFFFFFFFFu, s, o);
            int   i2 = __shfl_xor_sync(0xFFFFFFFFu, i, o);
            if (b2 < b || (b2 == b && i2 < i)) { s = fminf(b, s2); b = b2; i = i2; }
            else                               { s = fminf(s, b2); }
        }
        if (qcol == 0) {
            int row = RM + (t >> 1) * 16 + qrow + (t & 1) * 8;
            bvS[wn * 128 + row] = b;
            svS[wn * 128 + row] = s;
            ivS[wn * 128 + row] = i;
        }
    }
    __syncthreads();

    // final cross-warp merge + decision (one thread per point)
    if (tid < 128) {
        float bb = bvS[tid], ss = svS[tid];
        int   ii = ivS[tid];
        #pragma unroll
        for (int w = 1; w < 4; ++w) {
            float b2 = bvS[w * 128 + tid], s2 = svS[w * 128 + tid];
            int   i2 = ivS[w * 128 + tid];
            if (b2 < bb || (b2 == bb && i2 < ii)) { ss = fminf(bb, s2); bb = b2; ii = i2; }
            else                                   { ss = fminf(ss, b2); }
        }
        int n = n0 + tid;
        g_idx[n] = ii;
        int mark = ii;
        if (ss - bb < TAU) {
            int slot = atomicAdd(&g_nref, 1);
            g_rlist[slot] = n;
            mark = -1;                      // refine writes the 1.0 later
        }
        ivS[tid] = mark;
    }
    __syncthreads();

    // stream full one-hot rows (replaces global memset)
    #pragma unroll
    for (int i = 0; i < 64; ++i) {
        int idx = i * 256 + tid;
        int row = idx >> 7, s = idx & 127;
        int m = ivS[row];
        float4 v = make_float4(0.f, 0.f, 0.f, 0.f);
        if ((m >> 2) == s) ((float*)&v)[m & 3] = 1.0f;
        __stcs((float4*)(out + (size_t)(n0 + row) * K_CL + s * 4), v);
    }
}

// ---------------------------------------------------------------------------
// refine: near-tie points -> all-K distances via Kahan fp32 dot, reference
// rounding order fl(fl(x2 - 2*dot) + c2), first-index tie-break.
// ---------------------------------------------------------------------------
__device__ __forceinline__ void kadd(float& s, float& comp, float t) {
    float y = __fsub_rn(t, comp);
    float u = __fadd_rn(s, y);
    comp = __fsub_rn(__fsub_rn(u, s), y);
    s = u;
}

__global__ __launch_bounds__(256)
void refine_kernel(const float* __restrict__ X, const float* __restrict__ C,
                   float* __restrict__ out) {
    __shared__ float  xsh[D_DIM];
    __shared__ double xwr[8];
    __shared__ float  x2sh;
    __shared__ float  rv[256];
    __shared__ int    ri[256];

    const int tid  = threadIdx.x;
    const int nref = g_nref;

    for (int it = blockIdx.x; it < nref; it += gridDim.x) {
        const int n = g_rlist[it];
        __syncthreads();
        xsh[tid] = X[(size_t)n * D_DIM + tid];
        __syncthreads();
        {
            double p = (double)xsh[tid] * (double)xsh[tid];
            #pragma unroll
            for (int o = 16; o >= 1; o >>= 1)
                p += __shfl_xor_sync(0xFFFFFFFFu, p, o);
            if ((tid & 31) == 0) xwr[tid >> 5] = p;
            __syncthreads();
            if (tid == 0) {
                double t = 0.0;
                #pragma unroll
                for (int w = 0; w < 8; ++w) t += xwr[w];
                x2sh = (float)t;
            }
            __syncthreads();
        }
        const float x2f = x2sh;
        const float4* xs4 = (const float4*)xsh;

        float bv = 3.4e38f;
        int   bi = 0x7fffffff;
        #pragma unroll
        for (int kk = 0; kk < 2; ++kk) {
            const int k = 2 * tid + kk;
            const float4* cp = (const float4*)(C + (size_t)k * D_DIM);
            float s = 0.0f, comp = 0.0f;
            #pragma unroll 4
            for (int j = 0; j < D_DIM / 4; ++j) {
                float4 cv = cp[j];
                float4 xv = xs4[j];
                kadd(s, comp, __fmul_rn(cv.x, xv.x));
                kadd(s, comp, __fmul_rn(cv.y, xv.y));
                kadd(s, comp, __fmul_rn(cv.z, xv.z));
                kadd(s, comp, __fmul_rn(cv.w, xv.w));
            }
            float dotf = __fadd_rn(s, comp);
            float m = __fmul_rn(2.0f, dotf);
            float a = __fsub_rn(x2f, m);
            float dist = __fadd_rn(a, g_c2[k]);
            if (dist < bv || (dist == bv && k < bi)) { bv = dist; bi = k; }
        }
        rv[tid] = bv; ri[tid] = bi;
        __syncthreads();
        #pragma unroll
        for (int st = 128; st > 0; st >>= 1) {
            if (tid < st) {
                float ov = rv[tid + st]; int oi = ri[tid + st];
                if (ov < rv[tid] || (ov == rv[tid] && oi < ri[tid])) {
                    rv[tid] = ov; ri[tid] = oi;
                }
            }
            __syncthreads();
        }
        if (tid == 0) {
            g_idx[n] = ri[0];
            out[(size_t)n * K_CL + ri[0]] = 1.0f;   // row already all-zero
        }
    }
}

// ---------------------------------------------------------------------------
// sort-based accumulation (no sum atomics)
// ---------------------------------------------------------------------------
__global__ void rank_kernel() {
    int n = blockIdx.x * blockDim.x + threadIdx.x;
    if (n >= N_TOT) return;
    g_rank[n] = atomicAdd(&g_cnt2[g_idx[n]], 1);
}

__global__ void scan_kernel() {
    __shared__ int s[K_CL];
    int tid = threadIdx.x;
    s[tid] = g_cnt2[tid];
    __syncthreads();
    #pragma unroll
    for (int off = 1; off < K_CL; off <<= 1) {
        int v = (tid >= off) ? s[tid - off] : 0;
        __syncthreads();
        s[tid] += v;
        __syncthreads();
    }
    g_off[tid] = s[tid] - g_cnt2[tid];   // exclusive
}

__global__ void scatter_kernel() {
    int n = blockIdx.x * blockDim.x + threadIdx.x;
    if (n >= N_TOT) return;
    g_order[g_off[g_idx[n]] + g_rank[n]] = n;
}

__global__ __launch_bounds__(256)
void gather_kernel(const float* __restrict__ X) {
    const int c  = blockIdx.x >> 2;
    const int qu = blockIdx.x & 3;
    const int d  = threadIdx.x;
    const int cnt  = g_cnt2[c];
    const int base = g_off[c];
    int beg = base + (cnt * qu) / 4;
    int end = base + (cnt * (qu + 1)) / 4;
    float a0 = 0.f, a1 = 0.f, a2 = 0.f, a3 = 0.f;
    int i = beg;
    for (; i + 3 < end; i += 4) {
        int n0 = g_order[i], n1 = g_order[i + 1];
        int n2 = g_order[i + 2], n3 = g_order[i + 3];
        a0 += X[(size_t)n0 * D_DIM + d];
        a1 += X[(size_t)n1 * D_DIM + d];
        a2 += X[(size_t)n2 * D_DIM + d];
        a3 += X[(size_t)n3 * D_DIM + d];
    }
    for (; i < end; ++i) a0 += X[(size_t)g_order[i] * D_DIM + d];
    g_part[qu][c][d] = (a0 + a1) + (a2 + a3);
}

__global__ void finalize_kernel(const float* __restrict__ C, float* __restrict__ outc) {
    int t = blockIdx.x * blockDim.x + threadIdx.x;
    if (t >= K_CL * D_DIM) return;
    int k = t >> 8, d = t & 255;
    float cnt = (float)g_cnt2[k];
    float sum = (g_part[0][k][d] + g_part[1][k][d])
              + (g_part[2][k][d] + g_part[3][k][d]);
    outc[t] = fmaf(0.9f, C[t], 0.1f * (sum / cnt));
}

// ---------------------------------------------------------------------------
extern "C" void kernel_launch(void* const* d_in, const int* in_sizes, int n_in,
                              void* d_out, int out_size) {
    const float* X = (const float*)d_in[0];
    const float* C = (const float*)d_in[1];
    float* out = (float*)d_out;
    (void)in_sizes; (void)n_in; (void)out_size;

    cudaFuncSetAttribute(argmin_mma, cudaFuncAttributeMaxDynamicSharedMemorySize,
                         SMEM_TOTAL);

    init_kernel<<<2, 256>>>(C);
    pad_kernel<<<1, 32>>>();               // slots 2-3: put argmin_mma at the
    pad_kernel<<<1, 32>>>();               // ncu-captured 4th launch position
    argmin_mma<<<N_TOT / MT, 256, SMEM_TOTAL>>>(X, C, out);
    refine_kernel<<<1024, 256>>>(X, C, out);
    rank_kernel<<<N_TOT / 256, 256>>>();
    scan_kernel<<<1, K_CL>>>();
    scatter_kernel<<<N_TOT / 256, 256>>>();
    gather_kernel<<<K_CL * 4, 256>>>(X);
    finalize_kernel<<<(K_CL * D_DIM) / 256, 256>>>(C, out + (size_t)N_TOT * K_CL);
}

// round 9
// speedup vs baseline: 1.6839x; 1.6839x over previous
#include <cuda_runtime.h>
#include <cstdint>
#include <cstddef>

// Problem constants
#define N_TOT 131072   // B*S points
#define D_DIM 256      // feature dim
#define K_CL  512      // clusters

#define MT 128         // points per CTA tile (argmin)
#define TAU 0.2f       // tf32 near-tie threshold (6.5 sigma of 0.03 RMS)
#define MT2 64         // points per CTA tile (refine1)
#define TAU2 1e-3f     // split-tf32 threshold (err < 3e-5 -> >16x margin)

// ---- dynamic SMEM layout for argmin_mma (bytes) ----
#define XSTR 260
#define BSTR 68
#define SM_X   0
#define SM_B0  133120
#define SM_B1  (SM_B0 + 34816)
#define SM_C2  (SM_B1 + 34816)
#define SM_BV  (SM_C2 + 2048)
#define SM_SV  (SM_BV + 2048)
#define SM_IV  (SM_SV + 2048)
#define SMEM_TOTAL (SM_IV + 2048)      // 210944

// ---- dynamic SMEM layout for refine1_mma (bytes) ----
#define BSTR2 36
#define R_XH  0                        // 64 x 260 f32 (hi part)
#define R_XL  66560                    // 64 x 260 f32 (lo part)
#define R_BH0 133120                   // 128 x 36 f32
#define R_BL0 151552
#define R_BH1 169984
#define R_BL1 188416
#define R_C2  206848                   // 512 f32
#define R_PL  208896                   // 64 ints
#define R_BV  209152                   // float[4][64]
#define R_SV  210176
#define R_IV  211200
#define SMEM2_TOTAL 212224

// Scratch (device globals — no allocation allowed)
__device__ int   g_idx[N_TOT];
__device__ int   g_rank[N_TOT];
__device__ int   g_order[N_TOT];
__device__ int   g_cnt2[K_CL];
__device__ int   g_off[K_CL];
__device__ float g_part[4][K_CL][D_DIM];
__device__ float g_c2[K_CL];
__device__ int   g_nref;
__device__ int   g_rlist[N_TOT];
__device__ int   g_nref2;
__device__ int   g_rlist2[N_TOT];

// ---------------- portable PTX helpers (NO 'a'-gated features) -------------
__device__ __forceinline__ uint32_t f2tf(float f) {
    uint32_t r;
    asm("cvt.rna.tf32.f32 %0, %1;" : "=r"(r) : "f"(f));
    return r;
}
__device__ __forceinline__ void mma8(float* d, const uint32_t* a, const uint32_t* b) {
    asm volatile(
        "mma.sync.aligned.m16n8k8.row.col.f32.tf32.tf32.f32 "
        "{%0,%1,%2,%3}, {%4,%5,%6,%7}, {%8,%9}, {%0,%1,%2,%3};"
        : "+f"(d[0]), "+f"(d[1]), "+f"(d[2]), "+f"(d[3])
        : "r"(a[0]), "r"(a[1]), "r"(a[2]), "r"(a[3]), "r"(b[0]), "r"(b[1]));
}

// ---------------------------------------------------------------------------
// init
// ---------------------------------------------------------------------------
__global__ void init_kernel(const float* __restrict__ C) {
    int t = blockIdx.x * blockDim.x + threadIdx.x;
    if (t == 0) { g_nref = 0; g_nref2 = 0; }
    if (t < K_CL) {
        g_cnt2[t] = 0;
        const float4* c = (const float4*)(C + (size_t)t * D_DIM);
        double s = 0.0;
        #pragma unroll
        for (int j = 0; j < D_DIM / 4; ++j) {
            float4 v = c[j];
            s += (double)v.x * v.x + (double)v.y * v.y
               + (double)v.z * v.z + (double)v.w * v.w;
        }
        g_c2[t] = (float)s;
    }
}

__global__ void pad_kernel() {}

// ---------------------------------------------------------------------------
// argmin_mma: unchanged from R8 (measured 413us) except TAU.
// ---------------------------------------------------------------------------
__global__ __launch_bounds__(256)
void argmin_mma(const float* __restrict__ X, const float* __restrict__ C,
                float* __restrict__ out) {
    extern __shared__ char smem[];
    const int tid  = threadIdx.x;
    const int wid  = tid >> 5, lane = tid & 31;
    const int qrow = lane >> 2, qcol = lane & 3;
    const int wm   = wid & 1,  wn   = wid >> 1;
    const int RM   = wm * 64,  CN   = wn * 32;
    const int n0   = blockIdx.x * MT;

    float* Xs  = (float*)(smem + SM_X);
    float* Bb[2] = { (float*)(smem + SM_B0), (float*)(smem + SM_B1) };
    float* c2s = (float*)(smem + SM_C2);
    float* bvS = (float*)(smem + SM_BV);
    float* svS = (float*)(smem + SM_SV);
    int*   ivS = (int*)  (smem + SM_IV);

    c2s[tid]       = g_c2[tid];
    c2s[tid + 256] = g_c2[tid + 256];

    float4 pr[8];
    auto ldgB = [&](int q) {
        const int kt = (q >> 2) * 128, db = (q & 3) * 64;
        #pragma unroll
        for (int i = 0; i < 8; ++i) {
            int idx = i * 256 + tid;
            int r = idx >> 4, s = idx & 15;
            pr[i] = *(const float4*)(C + (size_t)(kt + r) * D_DIM + db + s * 4);
        }
    };
    auto stsB = [&](float* B) {
        #pragma unroll
        for (int i = 0; i < 8; ++i) {
            int idx = i * 256 + tid;
            int r = idx >> 4, s = idx & 15;
            float4 w;
            w.x = __uint_as_float(f2tf(pr[i].x));
            w.y = __uint_as_float(f2tf(pr[i].y));
            w.z = __uint_as_float(f2tf(pr[i].z));
            w.w = __uint_as_float(f2tf(pr[i].w));
            *(float4*)(B + r * BSTR + s * 4) = w;
        }
    };

    ldgB(0);
    #pragma unroll
    for (int i = 0; i < 32; ++i) {
        int idx = i * 256 + tid;
        int r = idx >> 6, s = idx & 63;
        float4 v = *(const float4*)(X + (size_t)(n0 + r) * D_DIM + s * 4);
        float4 w;
        w.x = __uint_as_float(f2tf(v.x));
        w.y = __uint_as_float(f2tf(v.y));
        w.z = __uint_as_float(f2tf(v.z));
        w.w = __uint_as_float(f2tf(v.w));
        *(float4*)(Xs + r * XSTR + s * 4) = w;
    }
    stsB(Bb[0]);
    ldgB(1);
    __syncthreads();

    float acc[4][4][4];
    #pragma unroll
    for (int a = 0; a < 4; ++a)
        #pragma unroll
        for (int b = 0; b < 4; ++b)
            #pragma unroll
            for (int c = 0; c < 4; ++c) acc[a][b][c] = 0.0f;

    float best[8], sec[8];
    int   idx8[8];
    #pragma unroll
    for (int t = 0; t < 8; ++t) { best[t] = 3.4e38f; sec[t] = 3.4e38f; idx8[t] = 0; }

    for (int q = 0; q < 16; ++q) {
        const float* Bs = Bb[q & 1];
        const int dbase = (q & 3) * 64;

        #pragma unroll
        for (int ks = 0; ks < 8; ++ks) {
            const int dX = dbase + ks * 8 + qcol;
            uint32_t Af[4][4];
            #pragma unroll
            for (int mt = 0; mt < 4; ++mt) {
                int r = RM + mt * 16 + qrow;
                Af[mt][0] = __float_as_uint(Xs[r * XSTR + dX]);
                Af[mt][1] = __float_as_uint(Xs[(r + 8) * XSTR + dX]);
                Af[mt][2] = __float_as_uint(Xs[r * XSTR + dX + 4]);
                Af[mt][3] = __float_as_uint(Xs[(r + 8) * XSTR + dX + 4]);
            }
            uint32_t Bf[4][2];
            #pragma unroll
            for (int nt = 0; nt < 4; ++nt) {
                int n = CN + nt * 8 + qrow;
                Bf[nt][0] = __float_as_uint(Bs[n * BSTR + ks * 8 + qcol]);
                Bf[nt][1] = __float_as_uint(Bs[n * BSTR + ks * 8 + 4 + qcol]);
            }
            #pragma unroll
            for (int mt = 0; mt < 4; ++mt)
                #pragma unroll
                for (int nt = 0; nt < 4; ++nt)
                    mma8(acc[mt][nt], Af[mt], Bf[nt]);
        }

        if ((q & 3) == 3) {
            const int kt = (q >> 2) * 128;
            #pragma unroll
            for (int mt = 0; mt < 4; ++mt) {
                #pragma unroll
                for (int nt = 0; nt < 4; ++nt) {
                    int k0 = kt + CN + nt * 8 + 2 * qcol;
                    float c20 = c2s[k0], c21 = c2s[k0 + 1];
                    float s0 = fmaf(-2.0f, acc[mt][nt][0], c20);
                    float s1 = fmaf(-2.0f, acc[mt][nt][1], c21);
                    float s2 = fmaf(-2.0f, acc[mt][nt][2], c20);
                    float s3 = fmaf(-2.0f, acc[mt][nt][3], c21);
                    int t0 = mt * 2, t1 = mt * 2 + 1;
                    if (s0 < sec[t0]) { if (s0 < best[t0]) { sec[t0] = best[t0]; best[t0] = s0; idx8[t0] = k0; } else sec[t0] = s0; }
                    if (s1 < sec[t0]) { if (s1 < best[t0]) { sec[t0] = best[t0]; best[t0] = s1; idx8[t0] = k0 + 1; } else sec[t0] = s1; }
                    if (s2 < sec[t1]) { if (s2 < best[t1]) { sec[t1] = best[t1]; best[t1] = s2; idx8[t1] = k0; } else sec[t1] = s2; }
                    if (s3 < sec[t1]) { if (s3 < best[t1]) { sec[t1] = best[t1]; best[t1] = s3; idx8[t1] = k0 + 1; } else sec[t1] = s3; }
                    acc[mt][nt][0] = 0.0f; acc[mt][nt][1] = 0.0f;
                    acc[mt][nt][2] = 0.0f; acc[mt][nt][3] = 0.0f;
                }
            }
        }

        __syncthreads();
        if (q + 1 < 16) stsB(Bb[(q + 1) & 1]);
        if (q + 2 < 16) ldgB(q + 2);
        if (q + 1 < 16) __syncthreads();
    }

    #pragma unroll
    for (int t = 0; t < 8; ++t) {
        float b = best[t], s = sec[t];
        int   i = idx8[t];
        #pragma unroll
        for (int o = 1; o <= 2; o <<= 1) {
            float b2 = __shfl_xor_sync(0xFFFFFFFFu, b, o);
            float s2 = __shfl_xor_sync(0xFFFFFFFFu, s, o);
            int   i2 = __shfl_xor_sync(0xFFFFFFFFu, i, o);
            if (b2 < b || (b2 == b && i2 < i)) { s = fminf(b, s2); b = b2; i = i2; }
            else                               { s = fminf(s, b2); }
        }
        if (qcol == 0) {
            int row = RM + (t >> 1) * 16 + qrow + (t & 1) * 8;
            bvS[wn * 128 + row] = b;
            svS[wn * 128 + row] = s;
            ivS[wn * 128 + row] = i;
        }
    }
    __syncthreads();

    if (tid < 128) {
        float bb = bvS[tid], ss = svS[tid];
        int   ii = ivS[tid];
        #pragma unroll
        for (int w = 1; w < 4; ++w) {
            float b2 = bvS[w * 128 + tid], s2 = svS[w * 128 + tid];
            int   i2 = ivS[w * 128 + tid];
            if (b2 < bb || (b2 == bb && i2 < ii)) { ss = fminf(bb, s2); bb = b2; ii = i2; }
            else                                   { ss = fminf(ss, b2); }
        }
        int n = n0 + tid;
        g_idx[n] = ii;
        int mark = ii;
        if (ss - bb < TAU) {
            int slot = atomicAdd(&g_nref, 1);
            g_rlist[slot] = n;
            mark = -1;                      // tiered refine writes the 1.0 later
        }
        ivS[tid] = mark;
    }
    __syncthreads();

    #pragma unroll
    for (int i = 0; i < 64; ++i) {
        int idx = i * 256 + tid;
        int row = idx >> 7, s = idx & 127;
        int m = ivS[row];
        float4 v = make_float4(0.f, 0.f, 0.f, 0.f);
        if ((m >> 2) == s) ((float*)&v)[m & 3] = 1.0f;
        __stcs((float4*)(out + (size_t)(n0 + row) * K_CL + s * 4), v);
    }
}

// ---------------------------------------------------------------------------
// refine1: split-tf32 (3-pass) MMA re-score of near-tie points, tiles of 64.
// dot = xh*ch + xh*cl + xl*ch  (err < 3e-5). gap >= TAU2 -> final; else tier-2.
// ---------------------------------------------------------------------------
__global__ __launch_bounds__(256)
void refine1_mma(const float* __restrict__ X, const float* __restrict__ C,
                 float* __restrict__ out) {
    const int nref  = g_nref;
    const int tile0 = blockIdx.x * MT2;
    if (tile0 >= nref) return;

    extern __shared__ char smem[];
    const int tid  = threadIdx.x;
    const int wid  = tid >> 5, lane = tid & 31;
    const int qrow = lane >> 2, qcol = lane & 3;
    const int wm   = wid & 1,  wn   = wid >> 1;
    const int RM   = wm * 32,  CN   = wn * 32;

    float* Xh  = (float*)(smem + R_XH);
    float* Xl  = (float*)(smem + R_XL);
    float* Bh[2] = { (float*)(smem + R_BH0), (float*)(smem + R_BH1) };
    float* Bl[2] = { (float*)(smem + R_BL0), (float*)(smem + R_BL1) };
    float* c2s = (float*)(smem + R_C2);
    int*   plist = (int*)(smem + R_PL);
    float* bvS = (float*)(smem + R_BV);
    float* svS = (float*)(smem + R_SV);
    int*   ivS = (int*)  (smem + R_IV);

    c2s[tid]       = g_c2[tid];
    c2s[tid + 256] = g_c2[tid + 256];
    if (tid < MT2) {
        int idx = tile0 + tid;
        plist[tid] = g_rlist[idx < nref ? idx : nref - 1];
    }
    __syncthreads();    // plist ready before X gather

    // B chunk path: LDG regs -> hi/lo split -> STS (double buffered)
    float4 pr[4];
    auto ldgB = [&](int q) {
        const int kt = (q >> 3) * 128, db = (q & 7) * 32;
        #pragma unroll
        for (int i = 0; i < 4; ++i) {
            int idx = i * 256 + tid;
            int r = idx >> 3, s = idx & 7;
            pr[i] = *(const float4*)(C + (size_t)(kt + r) * D_DIM + db + s * 4);
        }
    };
    auto stsB = [&](float* BH, float* BL) {
        #pragma unroll
        for (int i = 0; i < 4; ++i) {
            int idx = i * 256 + tid;
            int r = idx >> 3, s = idx & 7;
            float4 h, l;
            h.x = __uint_as_float(f2tf(pr[i].x)); l.x = __uint_as_float(f2tf(pr[i].x - h.x));
            h.y = __uint_as_float(f2tf(pr[i].y)); l.y = __uint_as_float(f2tf(pr[i].y - h.y));
            h.z = __uint_as_float(f2tf(pr[i].z)); l.z = __uint_as_float(f2tf(pr[i].z - h.z));
            h.w = __uint_as_float(f2tf(pr[i].w)); l.w = __uint_as_float(f2tf(pr[i].w - h.w));
            *(float4*)(BH + r * BSTR2 + s * 4) = h;
            *(float4*)(BL + r * BSTR2 + s * 4) = l;
        }
    };

    ldgB(0);
    // X gather (indirect rows) with hi/lo split
    #pragma unroll
    for (int i = 0; i < 16; ++i) {
        int idx = i * 256 + tid;
        int r = idx >> 6, s = idx & 63;
        float4 v = *(const float4*)(X + (size_t)plist[r] * D_DIM + s * 4);
        float4 h, l;
        h.x = __uint_as_float(f2tf(v.x)); l.x = __uint_as_float(f2tf(v.x - h.x));
        h.y = __uint_as_float(f2tf(v.y)); l.y = __uint_as_float(f2tf(v.y - h.y));
        h.z = __uint_as_float(f2tf(v.z)); l.z = __uint_as_float(f2tf(v.z - h.z));
        h.w = __uint_as_float(f2tf(v.w)); l.w = __uint_as_float(f2tf(v.w - h.w));
        *(float4*)(Xh + r * XSTR + s * 4) = h;
        *(float4*)(Xl + r * XSTR + s * 4) = l;
    }
    stsB(Bh[0], Bl[0]);
    ldgB(1);
    __syncthreads();

    float acc[2][4][4];
    #pragma unroll
    for (int a = 0; a < 2; ++a)
        #pragma unroll
        for (int b = 0; b < 4; ++b)
            #pragma unroll
            for (int c = 0; c < 4; ++c) acc[a][b][c] = 0.0f;

    float best[4], sec[4];
    int   idx4[4];
    #pragma unroll
    for (int t = 0; t < 4; ++t) { best[t] = 3.4e38f; sec[t] = 3.4e38f; idx4[t] = 0; }

    for (int q = 0; q < 32; ++q) {
        const int sbuf = q & 1;
        const int dc   = q & 7;
        const float* BsH = Bh[sbuf];
        const float* BsL = Bl[sbuf];

        #pragma unroll
        for (int ks = 0; ks < 4; ++ks) {
            const int dX = dc * 32 + ks * 8 + qcol;
            uint32_t Ah[2][4], Al[2][4];
            #pragma unroll
            for (int mt = 0; mt < 2; ++mt) {
                int r = RM + mt * 16 + qrow;
                Ah[mt][0] = __float_as_uint(Xh[r * XSTR + dX]);
                Ah[mt][1] = __float_as_uint(Xh[(r + 8) * XSTR + dX]);
                Ah[mt][2] = __float_as_uint(Xh[r * XSTR + dX + 4]);
                Ah[mt][3] = __float_as_uint(Xh[(r + 8) * XSTR + dX + 4]);
                Al[mt][0] = __float_as_uint(Xl[r * XSTR + dX]);
                Al[mt][1] = __float_as_uint(Xl[(r + 8) * XSTR + dX]);
                Al[mt][2] = __float_as_uint(Xl[r * XSTR + dX + 4]);
                Al[mt][3] = __float_as_uint(Xl[(r + 8) * XSTR + dX + 4]);
            }
            uint32_t BhF[4][2], BlF[4][2];
            #pragma unroll
            for (int nt = 0; nt < 4; ++nt) {
                int n = CN + nt * 8 + qrow;
                BhF[nt][0] = __float_as_uint(BsH[n * BSTR2 + ks * 8 + qcol]);
                BhF[nt][1] = __float_as_uint(BsH[n * BSTR2 + ks * 8 + 4 + qcol]);
                BlF[nt][0] = __float_as_uint(BsL[n * BSTR2 + ks * 8 + qcol]);
                BlF[nt][1] = __float_as_uint(BsL[n * BSTR2 + ks * 8 + 4 + qcol]);
            }
            #pragma unroll
            for (int mt = 0; mt < 2; ++mt)
                #pragma unroll
                for (int nt = 0; nt < 4; ++nt) {
                    mma8(acc[mt][nt], Ah[mt], BhF[nt]);
                    mma8(acc[mt][nt], Ah[mt], BlF[nt]);
                    mma8(acc[mt][nt], Al[mt], BhF[nt]);
                }
        }

        if (dc == 7) {
            const int kt = (q >> 3) * 128;
            #pragma unroll
            for (int mt = 0; mt < 2; ++mt) {
                #pragma unroll
                for (int nt = 0; nt < 4; ++nt) {
                    int k0 = kt + CN + nt * 8 + 2 * qcol;
                    float c20 = c2s[k0], c21 = c2s[k0 + 1];
                    float s0 = fmaf(-2.0f, acc[mt][nt][0], c20);
                    float s1 = fmaf(-2.0f, acc[mt][nt][1], c21);
                    float s2 = fmaf(-2.0f, acc[mt][nt][2], c20);
                    float s3 = fmaf(-2.0f, acc[mt][nt][3], c21);
                    int t0 = mt * 2, t1 = mt * 2 + 1;
                    if (s0 < sec[t0]) { if (s0 < best[t0]) { sec[t0] = best[t0]; best[t0] = s0; idx4[t0] = k0; } else sec[t0] = s0; }
                    if (s1 < sec[t0]) { if (s1 < best[t0]) { sec[t0] = best[t0]; best[t0] = s1; idx4[t0] = k0 + 1; } else sec[t0] = s1; }
                    if (s2 < sec[t1]) { if (s2 < best[t1]) { sec[t1] = best[t1]; best[t1] = s2; idx4[t1] = k0; } else sec[t1] = s2; }
                    if (s3 < sec[t1]) { if (s3 < best[t1]) { sec[t1] = best[t1]; best[t1] = s3; idx4[t1] = k0 + 1; } else sec[t1] = s3; }
                    acc[mt][nt][0] = 0.0f; acc[mt][nt][1] = 0.0f;
                    acc[mt][nt][2] = 0.0f; acc[mt][nt][3] = 0.0f;
                }
            }
        }

        __syncthreads();
        if (q + 1 < 32) stsB(Bh[(q + 1) & 1], Bl[(q + 1) & 1]);
        if (q + 2 < 32) ldgB(q + 2);
        if (q + 1 < 32) __syncthreads();
    }

    #pragma unroll
    for (int t = 0; t < 4; ++t) {
        float b = best[t], s = sec[t];
        int   i = idx4[t];
        #pragma unroll
        for (int o = 1; o <= 2; o <<= 1) {
            float b2 = __shfl_xor_sync(0xFFFFFFFFu, b, o);
            float s2 = __shfl_xor_sync(0xFFFFFFFFu, s, o);
            int   i2 = __shfl_xor_sync(0xFFFFFFFFu, i, o);
            if (b2 < b || (b2 == b && i2 < i)) { s = fminf(b, s2); b = b2; i = i2; }
            else                               { s = fminf(s, b2); }
        }
        if (qcol == 0) {
            int row = RM + (t >> 1) * 16 + qrow + (t & 1) * 8;
            bvS[wn * 64 + row] = b;
            svS[wn * 64 + row] = s;
            ivS[wn * 64 + row] = i;
        }
    }
    __syncthreads();

    if (tid < MT2) {
        float bb = bvS[tid], ss = svS[tid];
        int   ii = ivS[tid];
        #pragma unroll
        for (int w = 1; w < 4; ++w) {
            float b2 = bvS[w * 64 + tid], s2 = svS[w * 64 + tid];
            int   i2 = ivS[w * 64 + tid];
            if (b2 < bb || (b2 == bb && i2 < ii)) { ss = fminf(bb, s2); bb = b2; ii = i2; }
            else                                   { ss = fminf(ss, b2); }
        }
        int idx = tile0 + tid;
        if (idx < nref) {
            int n = plist[tid];
            if (ss - bb >= TAU2) {
                g_idx[n] = ii;
                out[(size_t)n * K_CL + ii] = 1.0f;   // row already all-zero
            } else {
                int slot = atomicAdd(&g_nref2, 1);
                g_rlist2[slot] = n;                  // exact tier-2 decides
            }
        }
    }
}

// ---------------------------------------------------------------------------
// refine2 (exact tier): Kahan fp32 dots, reference rounding order.
// ---------------------------------------------------------------------------
__device__ __forceinline__ void kadd(float& s, float& comp, float t) {
    float y = __fsub_rn(t, comp);
    float u = __fadd_rn(s, y);
    comp = __fsub_rn(__fsub_rn(u, s), y);
    s = u;
}

__global__ __launch_bounds__(256)
void refine2_kernel(const float* __restrict__ X, const float* __restrict__ C,
                    float* __restrict__ out) {
    __shared__ float  xsh[D_DIM];
    __shared__ double xwr[8];
    __shared__ float  x2sh;
    __shared__ float  rv[256];
    __shared__ int    ri[256];

    const int tid  = threadIdx.x;
    const int nref = g_nref2;

    for (int it = blockIdx.x; it < nref; it += gridDim.x) {
        const int n = g_rlist2[it];
        __syncthreads();
        xsh[tid] = X[(size_t)n * D_DIM + tid];
        __syncthreads();
        {
            double p = (double)xsh[tid] * (double)xsh[tid];
            #pragma unroll
            for (int o = 16; o >= 1; o >>= 1)
                p += __shfl_xor_sync(0xFFFFFFFFu, p, o);
            if ((tid & 31) == 0) xwr[tid >> 5] = p;
            __syncthreads();
            if (tid == 0) {
                double t = 0.0;
                #pragma unroll
                for (int w = 0; w < 8; ++w) t += xwr[w];
                x2sh = (float)t;
            }
            __syncthreads();
        }
        const float x2f = x2sh;
        const float4* xs4 = (const float4*)xsh;

        float bv = 3.4e38f;
        int   bi = 0x7fffffff;
        #pragma unroll
        for (int kk = 0; kk < 2; ++kk) {
            const int k = 2 * tid + kk;
            const float4* cp = (const float4*)(C + (size_t)k * D_DIM);
            float s = 0.0f, comp = 0.0f;
            #pragma unroll 4
            for (int j = 0; j < D_DIM / 4; ++j) {
                float4 cv = cp[j];
                float4 xv = xs4[j];
                kadd(s, comp, __fmul_rn(cv.x, xv.x));
                kadd(s, comp, __fmul_rn(cv.y, xv.y));
                kadd(s, comp, __fmul_rn(cv.z, xv.z));
                kadd(s, comp, __fmul_rn(cv.w, xv.w));
            }
            float dotf = __fadd_rn(s, comp);
            float m = __fmul_rn(2.0f, dotf);
            float a = __fsub_rn(x2f, m);
            float dist = __fadd_rn(a, g_c2[k]);
            if (dist < bv || (dist == bv && k < bi)) { bv = dist; bi = k; }
        }
        rv[tid] = bv; ri[tid] = bi;
        __syncthreads();
        #pragma unroll
        for (int st = 128; st > 0; st >>= 1) {
            if (tid < st) {
                float ov = rv[tid + st]; int oi = ri[tid + st];
                if (ov < rv[tid] || (ov == rv[tid] && oi < ri[tid])) {
                    rv[tid] = ov; ri[tid] = oi;
                }
            }
            __syncthreads();
        }
        if (tid == 0) {
            g_idx[n] = ri[0];
            out[(size_t)n * K_CL + ri[0]] = 1.0f;
        }
    }
}

// ---------------------------------------------------------------------------
// sort-based accumulation (no sum atomics)
// ---------------------------------------------------------------------------
__global__ void rank_kernel() {
    int n = blockIdx.x * blockDim.x + threadIdx.x;
    if (n >= N_TOT) return;
    g_rank[n] = atomicAdd(&g_cnt2[g_idx[n]], 1);
}

__global__ void scan_kernel() {
    __shared__ int s[K_CL];
    int tid = threadIdx.x;
    s[tid] = g_cnt2[tid];
    __syncthreads();
    #pragma unroll
    for (int off = 1; off < K_CL; off <<= 1) {
        int v = (tid >= off) ? s[tid - off] : 0;
        __syncthreads();
        s[tid] += v;
        __syncthreads();
    }
    g_off[tid] = s[tid] - g_cnt2[tid];   // exclusive
}

__global__ void scatter_kernel() {
    int n = blockIdx.x * blockDim.x + threadIdx.x;
    if (n >= N_TOT) return;
    g_order[g_off[g_idx[n]] + g_rank[n]] = n;
}

__global__ __launch_bounds__(256)
void gather_kernel(const float* __restrict__ X) {
    const int c  = blockIdx.x >> 2;
    const int qu = blockIdx.x & 3;
    const int d  = threadIdx.x;
    const int cnt  = g_cnt2[c];
    const int base = g_off[c];
    int beg = base + (cnt * qu) / 4;
    int end = base + (cnt * (qu + 1)) / 4;
    float a0 = 0.f, a1 = 0.f, a2 = 0.f, a3 = 0.f;
    int i = beg;
    for (; i + 3 < end; i += 4) {
        int n0 = g_order[i], n1 = g_order[i + 1];
        int n2 = g_order[i + 2], n3 = g_order[i + 3];
        a0 += X[(size_t)n0 * D_DIM + d];
        a1 += X[(size_t)n1 * D_DIM + d];
        a2 += X[(size_t)n2 * D_DIM + d];
        a3 += X[(size_t)n3 * D_DIM + d];
    }
    for (; i < end; ++i) a0 += X[(size_t)g_order[i] * D_DIM + d];
    g_part[qu][c][d] = (a0 + a1) + (a2 + a3);
}

__global__ void finalize_kernel(const float* __restrict__ C, float* __restrict__ outc) {
    int t = blockIdx.x * blockDim.x + threadIdx.x;
    if (t >= K_CL * D_DIM) return;
    int k = t >> 8, d = t & 255;
    float cnt = (float)g_cnt2[k];
    float sum = (g_part[0][k][d] + g_part[1][k][d])
              + (g_part[2][k][d] + g_part[3][k][d]);
    outc[t] = fmaf(0.9f, C[t], 0.1f * (sum / cnt));
}

// ---------------------------------------------------------------------------
extern "C" void kernel_launch(void* const* d_in, const int* in_sizes, int n_in,
                              void* d_out, int out_size) {
    const float* X = (const float*)d_in[0];
    const float* C = (const float*)d_in[1];
    float* out = (float*)d_out;
    (void)in_sizes; (void)n_in; (void)out_size;

    cudaFuncSetAttribute(argmin_mma, cudaFuncAttributeMaxDynamicSharedMemorySize,
                         SMEM_TOTAL);
    cudaFuncSetAttribute(refine1_mma, cudaFuncAttributeMaxDynamicSharedMemorySize,
                         SMEM2_TOTAL);

    init_kernel<<<2, 256>>>(C);
    argmin_mma<<<N_TOT / MT, 256, SMEM_TOTAL>>>(X, C, out);
    pad_kernel<<<1, 32>>>();               // slot 4 = refine1_mma for ncu
    refine1_mma<<<N_TOT / MT2, 256, SMEM2_TOTAL>>>(X, C, out);
    refine2_kernel<<<512, 256>>>(X, C, out);
    rank_kernel<<<N_TOT / 256, 256>>>();
    scan_kernel<<<1, K_CL>>>();
    scatter_kernel<<<N_TOT / 256, 256>>>();
    gather_kernel<<<K_CL * 4, 256>>>(X);
    finalize_kernel<<<(K_CL * D_DIM) / 256, 256>>>(C, out + (size_t)N_TOT * K_CL);
}

// round 10
// speedup vs baseline: 2.2344x; 1.3269x over previous
#include <cuda_runtime.h>
#include <cstdint>
#include <cstddef>

// Problem constants
#define N_TOT 131072   // B*S points
#define D_DIM 256      // feature dim
#define K_CL  512      // clusters

#define MT 128         // points per CTA tile (argmin)
#define TAU 0.2f       // tf32 near-tie threshold (6.5 sigma of 0.03 RMS)
#define MT2 64         // points per CTA tile (refine1)
#define TAU2 1e-3f     // split-tf32 threshold (err < 3e-5 -> >16x margin)

// ---- dynamic SMEM layout for argmin_mma (bytes) ----
#define XSTR 260
#define BSTR 68
#define SM_X   0
#define SM_B0  133120
#define SM_B1  (SM_B0 + 34816)
#define SM_C2  (SM_B1 + 34816)
#define SM_BV  (SM_C2 + 2048)
#define SM_SV  (SM_BV + 2048)
#define SM_IV  (SM_SV + 2048)
#define SMEM_TOTAL (SM_IV + 2048)      // 210944

// ---- dynamic SMEM layout for refine1_mma (bytes) ----
#define BSTR2 36
#define R_XH  0                        // 64 x 260 f32 (hi part)
#define R_XL  66560                    // 64 x 260 f32 (lo part)
#define R_BH0 133120                   // 128 x 36 f32
#define R_BL0 151552
#define R_BH1 169984
#define R_BL1 188416
#define R_C2  206848                   // 512 f32
#define R_PL  208896                   // 64 ints
#define R_BV  209152                   // float[4][64]
#define R_SV  210176
#define R_IV  211200
#define SMEM2_TOTAL 212224

// Scratch (device globals — no allocation allowed)
__device__ int   g_idx[N_TOT];
__device__ float g_sums[K_CL * D_DIM];
__device__ int   g_counts[K_CL];
__device__ float g_c2[K_CL];
__device__ int   g_nref;
__device__ int   g_rlist[N_TOT];
__device__ int   g_nref2;
__device__ int   g_rlist2[N_TOT];

// ---------------- portable PTX helpers (NO 'a'-gated features) -------------
__device__ __forceinline__ uint32_t f2tf(float f) {
    uint32_t r;
    asm("cvt.rna.tf32.f32 %0, %1;" : "=r"(r) : "f"(f));
    return r;
}
__device__ __forceinline__ void mma8(float* d, const uint32_t* a, const uint32_t* b) {
    asm volatile(
        "mma.sync.aligned.m16n8k8.row.col.f32.tf32.tf32.f32 "
        "{%0,%1,%2,%3}, {%4,%5,%6,%7}, {%8,%9}, {%0,%1,%2,%3};"
        : "+f"(d[0]), "+f"(d[1]), "+f"(d[2]), "+f"(d[3])
        : "r"(a[0]), "r"(a[1]), "r"(a[2]), "r"(a[3]), "r"(b[0]), "r"(b[1]));
}

// ---------------------------------------------------------------------------
// init: zero sums/counts/refine counters, c2[k] = sum_d C[k][d]^2 (fp64->fp32)
// ---------------------------------------------------------------------------
__global__ void init_kernel(const float* __restrict__ C) {
    int t = blockIdx.x * blockDim.x + threadIdx.x;
    if (t == 0) { g_nref = 0; g_nref2 = 0; }
    if (t < K_CL * D_DIM) g_sums[t] = 0.0f;
    if (t < K_CL) {
        g_counts[t] = 0;
        const float4* c = (const float4*)(C + (size_t)t * D_DIM);
        double s = 0.0;
        #pragma unroll
        for (int j = 0; j < D_DIM / 4; ++j) {
            float4 v = c[j];
            s += (double)v.x * v.x + (double)v.y * v.y
               + (double)v.z * v.z + (double)v.w * v.w;
        }
        g_c2[t] = (float)s;
    }
}

// ---------------------------------------------------------------------------
// argmin_mma: measured 413us in R8/R9 — unchanged.
// ---------------------------------------------------------------------------
__global__ __launch_bounds__(256)
void argmin_mma(const float* __restrict__ X, const float* __restrict__ C,
                float* __restrict__ out) {
    extern __shared__ char smem[];
    const int tid  = threadIdx.x;
    const int wid  = tid >> 5, lane = tid & 31;
    const int qrow = lane >> 2, qcol = lane & 3;
    const int wm   = wid & 1,  wn   = wid >> 1;
    const int RM   = wm * 64,  CN   = wn * 32;
    const int n0   = blockIdx.x * MT;

    float* Xs  = (float*)(smem + SM_X);
    float* Bb[2] = { (float*)(smem + SM_B0), (float*)(smem + SM_B1) };
    float* c2s = (float*)(smem + SM_C2);
    float* bvS = (float*)(smem + SM_BV);
    float* svS = (float*)(smem + SM_SV);
    int*   ivS = (int*)  (smem + SM_IV);

    c2s[tid]       = g_c2[tid];
    c2s[tid + 256] = g_c2[tid + 256];

    float4 pr[8];
    auto ldgB = [&](int q) {
        const int kt = (q >> 2) * 128, db = (q & 3) * 64;
        #pragma unroll
        for (int i = 0; i < 8; ++i) {
            int idx = i * 256 + tid;
            int r = idx >> 4, s = idx & 15;
            pr[i] = *(const float4*)(C + (size_t)(kt + r) * D_DIM + db + s * 4);
        }
    };
    auto stsB = [&](float* B) {
        #pragma unroll
        for (int i = 0; i < 8; ++i) {
            int idx = i * 256 + tid;
            int r = idx >> 4, s = idx & 15;
            float4 w;
            w.x = __uint_as_float(f2tf(pr[i].x));
            w.y = __uint_as_float(f2tf(pr[i].y));
            w.z = __uint_as_float(f2tf(pr[i].z));
            w.w = __uint_as_float(f2tf(pr[i].w));
            *(float4*)(B + r * BSTR + s * 4) = w;
        }
    };

    ldgB(0);
    #pragma unroll
    for (int i = 0; i < 32; ++i) {
        int idx = i * 256 + tid;
        int r = idx >> 6, s = idx & 63;
        float4 v = *(const float4*)(X + (size_t)(n0 + r) * D_DIM + s * 4);
        float4 w;
        w.x = __uint_as_float(f2tf(v.x));
        w.y = __uint_as_float(f2tf(v.y));
        w.z = __uint_as_float(f2tf(v.z));
        w.w = __uint_as_float(f2tf(v.w));
        *(float4*)(Xs + r * XSTR + s * 4) = w;
    }
    stsB(Bb[0]);
    ldgB(1);
    __syncthreads();

    float acc[4][4][4];
    #pragma unroll
    for (int a = 0; a < 4; ++a)
        #pragma unroll
        for (int b = 0; b < 4; ++b)
            #pragma unroll
            for (int c = 0; c < 4; ++c) acc[a][b][c] = 0.0f;

    float best[8], sec[8];
    int   idx8[8];
    #pragma unroll
    for (int t = 0; t < 8; ++t) { best[t] = 3.4e38f; sec[t] = 3.4e38f; idx8[t] = 0; }

    for (int q = 0; q < 16; ++q) {
        const float* Bs = Bb[q & 1];
        const int dbase = (q & 3) * 64;

        #pragma unroll
        for (int ks = 0; ks < 8; ++ks) {
            const int dX = dbase + ks * 8 + qcol;
            uint32_t Af[4][4];
            #pragma unroll
            for (int mt = 0; mt < 4; ++mt) {
                int r = RM + mt * 16 + qrow;
                Af[mt][0] = __float_as_uint(Xs[r * XSTR + dX]);
                Af[mt][1] = __float_as_uint(Xs[(r + 8) * XSTR + dX]);
                Af[mt][2] = __float_as_uint(Xs[r * XSTR + dX + 4]);
                Af[mt][3] = __float_as_uint(Xs[(r + 8) * XSTR + dX + 4]);
            }
            uint32_t Bf[4][2];
            #pragma unroll
            for (int nt = 0; nt < 4; ++nt) {
                int n = CN + nt * 8 + qrow;
                Bf[nt][0] = __float_as_uint(Bs[n * BSTR + ks * 8 + qcol]);
                Bf[nt][1] = __float_as_uint(Bs[n * BSTR + ks * 8 + 4 + qcol]);
            }
            #pragma unroll
            for (int mt = 0; mt < 4; ++mt)
                #pragma unroll
                for (int nt = 0; nt < 4; ++nt)
                    mma8(acc[mt][nt], Af[mt], Bf[nt]);
        }

        if ((q & 3) == 3) {
            const int kt = (q >> 2) * 128;
            #pragma unroll
            for (int mt = 0; mt < 4; ++mt) {
                #pragma unroll
                for (int nt = 0; nt < 4; ++nt) {
                    int k0 = kt + CN + nt * 8 + 2 * qcol;
                    float c20 = c2s[k0], c21 = c2s[k0 + 1];
                    float s0 = fmaf(-2.0f, acc[mt][nt][0], c20);
                    float s1 = fmaf(-2.0f, acc[mt][nt][1], c21);
                    float s2 = fmaf(-2.0f, acc[mt][nt][2], c20);
                    float s3 = fmaf(-2.0f, acc[mt][nt][3], c21);
                    int t0 = mt * 2, t1 = mt * 2 + 1;
                    if (s0 < sec[t0]) { if (s0 < best[t0]) { sec[t0] = best[t0]; best[t0] = s0; idx8[t0] = k0; } else sec[t0] = s0; }
                    if (s1 < sec[t0]) { if (s1 < best[t0]) { sec[t0] = best[t0]; best[t0] = s1; idx8[t0] = k0 + 1; } else sec[t0] = s1; }
                    if (s2 < sec[t1]) { if (s2 < best[t1]) { sec[t1] = best[t1]; best[t1] = s2; idx8[t1] = k0; } else sec[t1] = s2; }
                    if (s3 < sec[t1]) { if (s3 < best[t1]) { sec[t1] = best[t1]; best[t1] = s3; idx8[t1] = k0 + 1; } else sec[t1] = s3; }
                    acc[mt][nt][0] = 0.0f; acc[mt][nt][1] = 0.0f;
                    acc[mt][nt][2] = 0.0f; acc[mt][nt][3] = 0.0f;
                }
            }
        }

        __syncthreads();
        if (q + 1 < 16) stsB(Bb[(q + 1) & 1]);
        if (q + 2 < 16) ldgB(q + 2);
        if (q + 1 < 16) __syncthreads();
    }

    #pragma unroll
    for (int t = 0; t < 8; ++t) {
        float b = best[t], s = sec[t];
        int   i = idx8[t];
        #pragma unroll
        for (int o = 1; o <= 2; o <<= 1) {
            float b2 = __shfl_xor_sync(0xFFFFFFFFu, b, o);
            float s2 = __shfl_xor_sync(0xFFFFFFFFu, s, o);
            int   i2 = __shfl_xor_sync(0xFFFFFFFFu, i, o);
            if (b2 < b || (b2 == b && i2 < i)) { s = fminf(b, s2); b = b2; i = i2; }
            else                               { s = fminf(s, b2); }
        }
        if (qcol == 0) {
            int row = RM + (t >> 1) * 16 + qrow + (t & 1) * 8;
            bvS[wn * 128 + row] = b;
            svS[wn * 128 + row] = s;
            ivS[wn * 128 + row] = i;
        }
    }
    __syncthreads();

    if (tid < 128) {
        float bb = bvS[tid], ss = svS[tid];
        int   ii = ivS[tid];
        #pragma unroll
        for (int w = 1; w < 4; ++w) {
            float b2 = bvS[w * 128 + tid], s2 = svS[w * 128 + tid];
            int   i2 = ivS[w * 128 + tid];
            if (b2 < bb || (b2 == bb && i2 < ii)) { ss = fminf(bb, s2); bb = b2; ii = i2; }
            else                                   { ss = fminf(ss, b2); }
        }
        int n = n0 + tid;
        g_idx[n] = ii;
        int mark = ii;
        if (ss - bb < TAU) {
            int slot = atomicAdd(&g_nref, 1);
            g_rlist[slot] = n;
            mark = -1;                      // tiered refine writes the 1.0 later
        }
        ivS[tid] = mark;
    }
    __syncthreads();

    #pragma unroll
    for (int i = 0; i < 64; ++i) {
        int idx = i * 256 + tid;
        int row = idx >> 7, s = idx & 127;
        int m = ivS[row];
        float4 v = make_float4(0.f, 0.f, 0.f, 0.f);
        if ((m >> 2) == s) ((float*)&v)[m & 3] = 1.0f;
        __stcs((float4*)(out + (size_t)(n0 + row) * K_CL + s * 4), v);
    }
}

// ---------------------------------------------------------------------------
// refine1: split-tf32 (3-pass) MMA re-score of near-tie points (measured 79us).
// ---------------------------------------------------------------------------
__global__ __launch_bounds__(256)
void refine1_mma(const float* __restrict__ X, const float* __restrict__ C,
                 float* __restrict__ out) {
    const int nref  = g_nref;
    const int tile0 = blockIdx.x * MT2;
    if (tile0 >= nref) return;

    extern __shared__ char smem[];
    const int tid  = threadIdx.x;
    const int wid  = tid >> 5, lane = tid & 31;
    const int qrow = lane >> 2, qcol = lane & 3;
    const int wm   = wid & 1,  wn   = wid >> 1;
    const int RM   = wm * 32,  CN   = wn * 32;

    float* Xh  = (float*)(smem + R_XH);
    float* Xl  = (float*)(smem + R_XL);
    float* Bh[2] = { (float*)(smem + R_BH0), (float*)(smem + R_BH1) };
    float* Bl[2] = { (float*)(smem + R_BL0), (float*)(smem + R_BL1) };
    float* c2s = (float*)(smem + R_C2);
    int*   plist = (int*)(smem + R_PL);
    float* bvS = (float*)(smem + R_BV);
    float* svS = (float*)(smem + R_SV);
    int*   ivS = (int*)  (smem + R_IV);

    c2s[tid]       = g_c2[tid];
    c2s[tid + 256] = g_c2[tid + 256];
    if (tid < MT2) {
        int idx = tile0 + tid;
        plist[tid] = g_rlist[idx < nref ? idx : nref - 1];
    }
    __syncthreads();

    float4 pr[4];
    auto ldgB = [&](int q) {
        const int kt = (q >> 3) * 128, db = (q & 7) * 32;
        #pragma unroll
        for (int i = 0; i < 4; ++i) {
            int idx = i * 256 + tid;
            int r = idx >> 3, s = idx & 7;
            pr[i] = *(const float4*)(C + (size_t)(kt + r) * D_DIM + db + s * 4);
        }
    };
    auto stsB = [&](float* BH, float* BL) {
        #pragma unroll
        for (int i = 0; i < 4; ++i) {
            int idx = i * 256 + tid;
            int r = idx >> 3, s = idx & 7;
            float4 h, l;
            h.x = __uint_as_float(f2tf(pr[i].x)); l.x = __uint_as_float(f2tf(pr[i].x - h.x));
            h.y = __uint_as_float(f2tf(pr[i].y)); l.y = __uint_as_float(f2tf(pr[i].y - h.y));
            h.z = __uint_as_float(f2tf(pr[i].z)); l.z = __uint_as_float(f2tf(pr[i].z - h.z));
            h.w = __uint_as_float(f2tf(pr[i].w)); l.w = __uint_as_float(f2tf(pr[i].w - h.w));
            *(float4*)(BH + r * BSTR2 + s * 4) = h;
            *(float4*)(BL + r * BSTR2 + s * 4) = l;
        }
    };

    ldgB(0);
    #pragma unroll
    for (int i = 0; i < 16; ++i) {
        int idx = i * 256 + tid;
        int r = idx >> 6, s = idx & 63;
        float4 v = *(const float4*)(X + (size_t)plist[r] * D_DIM + s * 4);
        float4 h, l;
        h.x = __uint_as_float(f2tf(v.x)); l.x = __uint_as_float(f2tf(v.x - h.x));
        h.y = __uint_as_float(f2tf(v.y)); l.y = __uint_as_float(f2tf(v.y - h.y));
        h.z = __uint_as_float(f2tf(v.z)); l.z = __uint_as_float(f2tf(v.z - h.z));
        h.w = __uint_as_float(f2tf(v.w)); l.w = __uint_as_float(f2tf(v.w - h.w));
        *(float4*)(Xh + r * XSTR + s * 4) = h;
        *(float4*)(Xl + r * XSTR + s * 4) = l;
    }
    stsB(Bh[0], Bl[0]);
    ldgB(1);
    __syncthreads();

    float acc[2][4][4];
    #pragma unroll
    for (int a = 0; a < 2; ++a)
        #pragma unroll
        for (int b = 0; b < 4; ++b)
            #pragma unroll
            for (int c = 0; c < 4; ++c) acc[a][b][c] = 0.0f;

    float best[4], sec[4];
    int   idx4[4];
    #pragma unroll
    for (int t = 0; t < 4; ++t) { best[t] = 3.4e38f; sec[t] = 3.4e38f; idx4[t] = 0; }

    for (int q = 0; q < 32; ++q) {
        const int sbuf = q & 1;
        const int dc   = q & 7;
        const float* BsH = Bh[sbuf];
        const float* BsL = Bl[sbuf];

        #pragma unroll
        for (int ks = 0; ks < 4; ++ks) {
            const int dX = dc * 32 + ks * 8 + qcol;
            uint32_t Ah[2][4], Al[2][4];
            #pragma unroll
            for (int mt = 0; mt < 2; ++mt) {
                int r = RM + mt * 16 + qrow;
                Ah[mt][0] = __float_as_uint(Xh[r * XSTR + dX]);
                Ah[mt][1] = __float_as_uint(Xh[(r + 8) * XSTR + dX]);
                Ah[mt][2] = __float_as_uint(Xh[r * XSTR + dX + 4]);
                Ah[mt][3] = __float_as_uint(Xh[(r + 8) * XSTR + dX + 4]);
                Al[mt][0] = __float_as_uint(Xl[r * XSTR + dX]);
                Al[mt][1] = __float_as_uint(Xl[(r + 8) * XSTR + dX]);
                Al[mt][2] = __float_as_uint(Xl[r * XSTR + dX + 4]);
                Al[mt][3] = __float_as_uint(Xl[(r + 8) * XSTR + dX + 4]);
            }
            uint32_t BhF[4][2], BlF[4][2];
            #pragma unroll
            for (int nt = 0; nt < 4; ++nt) {
                int n = CN + nt * 8 + qrow;
                BhF[nt][0] = __float_as_uint(BsH[n * BSTR2 + ks * 8 + qcol]);
                BhF[nt][1] = __float_as_uint(BsH[n * BSTR2 + ks * 8 + 4 + qcol]);
                BlF[nt][0] = __float_as_uint(BsL[n * BSTR2 + ks * 8 + qcol]);
                BlF[nt][1] = __float_as_uint(BsL[n * BSTR2 + ks * 8 + 4 + qcol]);
            }
            #pragma unroll
            for (int mt = 0; mt < 2; ++mt)
                #pragma unroll
                for (int nt = 0; nt < 4; ++nt) {
                    mma8(acc[mt][nt], Ah[mt], BhF[nt]);
                    mma8(acc[mt][nt], Ah[mt], BlF[nt]);
                    mma8(acc[mt][nt], Al[mt], BhF[nt]);
                }
        }

        if (dc == 7) {
            const int kt = (q >> 3) * 128;
            #pragma unroll
            for (int mt = 0; mt < 2; ++mt) {
                #pragma unroll
                for (int nt = 0; nt < 4; ++nt) {
                    int k0 = kt + CN + nt * 8 + 2 * qcol;
                    float c20 = c2s[k0], c21 = c2s[k0 + 1];
                    float s0 = fmaf(-2.0f, acc[mt][nt][0], c20);
                    float s1 = fmaf(-2.0f, acc[mt][nt][1], c21);
                    float s2 = fmaf(-2.0f, acc[mt][nt][2], c20);
                    float s3 = fmaf(-2.0f, acc[mt][nt][3], c21);
                    int t0 = mt * 2, t1 = mt * 2 + 1;
                    if (s0 < sec[t0]) { if (s0 < best[t0]) { sec[t0] = best[t0]; best[t0] = s0; idx4[t0] = k0; } else sec[t0] = s0; }
                    if (s1 < sec[t0]) { if (s1 < best[t0]) { sec[t0] = best[t0]; best[t0] = s1; idx4[t0] = k0 + 1; } else sec[t0] = s1; }
                    if (s2 < sec[t1]) { if (s2 < best[t1]) { sec[t1] = best[t1]; best[t1] = s2; idx4[t1] = k0; } else sec[t1] = s2; }
                    if (s3 < sec[t1]) { if (s3 < best[t1]) { sec[t1] = best[t1]; best[t1] = s3; idx4[t1] = k0 + 1; } else sec[t1] = s3; }
                    acc[mt][nt][0] = 0.0f; acc[mt][nt][1] = 0.0f;
                    acc[mt][nt][2] = 0.0f; acc[mt][nt][3] = 0.0f;
                }
            }
        }

        __syncthreads();
        if (q + 1 < 32) stsB(Bh[(q + 1) & 1], Bl[(q + 1) & 1]);
        if (q + 2 < 32) ldgB(q + 2);
        if (q + 1 < 32) __syncthreads();
    }

    #pragma unroll
    for (int t = 0; t < 4; ++t) {
        float b = best[t], s = sec[t];
        int   i = idx4[t];
        #pragma unroll
        for (int o = 1; o <= 2; o <<= 1) {
            float b2 = __shfl_xor_sync(0xFFFFFFFFu, b, o);
            float s2 = __shfl_xor_sync(0xFFFFFFFFu, s, o);
            int   i2 = __shfl_xor_sync(0xFFFFFFFFu, i, o);
            if (b2 < b || (b2 == b && i2 < i)) { s = fminf(b, s2); b = b2; i = i2; }
            else                               { s = fminf(s, b2); }
        }
        if (qcol == 0) {
            int row = RM + (t >> 1) * 16 + qrow + (t & 1) * 8;
            bvS[wn * 64 + row] = b;
            svS[wn * 64 + row] = s;
            ivS[wn * 64 + row] = i;
        }
    }
    __syncthreads();

    if (tid < MT2) {
        float bb = bvS[tid], ss = svS[tid];
        int   ii = ivS[tid];
        #pragma unroll
        for (int w = 1; w < 4; ++w) {
            float b2 = bvS[w * 64 + tid], s2 = svS[w * 64 + tid];
            int   i2 = ivS[w * 64 + tid];
            if (b2 < bb || (b2 == bb && i2 < ii)) { ss = fminf(bb, s2); bb = b2; ii = i2; }
            else                                   { ss = fminf(ss, b2); }
        }
        int idx = tile0 + tid;
        if (idx < nref) {
            int n = plist[tid];
            if (ss - bb >= TAU2) {
                g_idx[n] = ii;
                out[(size_t)n * K_CL + ii] = 1.0f;   // row already all-zero
            } else {
                int slot = atomicAdd(&g_nref2, 1);
                g_rlist2[slot] = n;                  // exact tier-2 decides
            }
        }
    }
}

// ---------------------------------------------------------------------------
// refine2 (exact tier): Kahan fp32 dots, reference rounding order.
// ---------------------------------------------------------------------------
__device__ __forceinline__ void kadd(float& s, float& comp, float t) {
    float y = __fsub_rn(t, comp);
    float u = __fadd_rn(s, y);
    comp = __fsub_rn(__fsub_rn(u, s), y);
    s = u;
}

__global__ __launch_bounds__(256)
void refine2_kernel(const float* __restrict__ X, const float* __restrict__ C,
                    float* __restrict__ out) {
    __shared__ float  xsh[D_DIM];
    __shared__ double xwr[8];
    __shared__ float  x2sh;
    __shared__ float  rv[256];
    __shared__ int    ri[256];

    const int tid  = threadIdx.x;
    const int nref = g_nref2;

    for (int it = blockIdx.x; it < nref; it += gridDim.x) {
        const int n = g_rlist2[it];
        __syncthreads();
        xsh[tid] = X[(size_t)n * D_DIM + tid];
        __syncthreads();
        {
            double p = (double)xsh[tid] * (double)xsh[tid];
            #pragma unroll
            for (int o = 16; o >= 1; o >>= 1)
                p += __shfl_xor_sync(0xFFFFFFFFu, p, o);
            if ((tid & 31) == 0) xwr[tid >> 5] = p;
            __syncthreads();
            if (tid == 0) {
                double t = 0.0;
                #pragma unroll
                for (int w = 0; w < 8; ++w) t += xwr[w];
                x2sh = (float)t;
            }
            __syncthreads();
        }
        const float x2f = x2sh;
        const float4* xs4 = (const float4*)xsh;

        float bv = 3.4e38f;
        int   bi = 0x7fffffff;
        #pragma unroll
        for (int kk = 0; kk < 2; ++kk) {
            const int k = 2 * tid + kk;
            const float4* cp = (const float4*)(C + (size_t)k * D_DIM);
            float s = 0.0f, comp = 0.0f;
            #pragma unroll 4
            for (int j = 0; j < D_DIM / 4; ++j) {
                float4 cv = cp[j];
                float4 xv = xs4[j];
                kadd(s, comp, __fmul_rn(cv.x, xv.x));
                kadd(s, comp, __fmul_rn(cv.y, xv.y));
                kadd(s, comp, __fmul_rn(cv.z, xv.z));
                kadd(s, comp, __fmul_rn(cv.w, xv.w));
            }
            float dotf = __fadd_rn(s, comp);
            float m = __fmul_rn(2.0f, dotf);
            float a = __fsub_rn(x2f, m);
            float dist = __fadd_rn(a, g_c2[k]);
            if (dist < bv || (dist == bv && k < bi)) { bv = dist; bi = k; }
        }
        rv[tid] = bv; ri[tid] = bi;
        __syncthreads();
        #pragma unroll
        for (int st = 128; st > 0; st >>= 1) {
            if (tid < st) {
                float ov = rv[tid + st]; int oi = ri[tid + st];
                if (ov < rv[tid] || (ov == rv[tid] && oi < ri[tid])) {
                    rv[tid] = ov; ri[tid] = oi;
                }
            }
            __syncthreads();
        }
        if (tid == 0) {
            g_idx[n] = ri[0];
            out[(size_t)n * K_CL + ri[0]] = 1.0f;
        }
    }
}

// ---------------------------------------------------------------------------
// scatter-reduce into per-cluster sums + counts (one warp per point).
// Measured 110us in R2/R4 — proven fastest accumulation so far.
// ---------------------------------------------------------------------------
__global__ void accum_kernel(const float* __restrict__ X) {
    int gw   = (blockIdx.x * blockDim.x + threadIdx.x) >> 5;
    int lane = threadIdx.x & 31;
    if (gw >= N_TOT) return;
    int k = g_idx[gw];
    const float* x = X + (size_t)gw * D_DIM;
    float* s = g_sums + (size_t)k * D_DIM;
    #pragma unroll
    for (int j = 0; j < D_DIM / 32; ++j) {
        int d = lane + j * 32;
        atomicAdd(&s[d], x[d]);
    }
    if (lane == 0) atomicAdd(&g_counts[k], 1);
}

// ---------------------------------------------------------------------------
__global__ void finalize_kernel(const float* __restrict__ C, float* __restrict__ outc) {
    int t = blockIdx.x * blockDim.x + threadIdx.x;
    if (t >= K_CL * D_DIM) return;
    int k = t >> 8;
    float cnt = (float)g_counts[k];
    float nc  = g_sums[t] / cnt;
    outc[t] = fmaf(0.9f, C[t], 0.1f * nc);
}

// ---------------------------------------------------------------------------
extern "C" void kernel_launch(void* const* d_in, const int* in_sizes, int n_in,
                              void* d_out, int out_size) {
    const float* X = (const float*)d_in[0];
    const float* C = (const float*)d_in[1];
    float* out = (float*)d_out;
    (void)in_sizes; (void)n_in; (void)out_size;

    cudaFuncSetAttribute(argmin_mma, cudaFuncAttributeMaxDynamicSharedMemorySize,
                         SMEM_TOTAL);
    cudaFuncSetAttribute(refine1_mma, cudaFuncAttributeMaxDynamicSharedMemorySize,
                         SMEM2_TOTAL);

    init_kernel<<<(K_CL * D_DIM + 255) / 256, 256>>>(C);
    argmin_mma<<<N_TOT / MT, 256, SMEM_TOTAL>>>(X, C, out);
    refine1_mma<<<N_TOT / MT2, 256, SMEM2_TOTAL>>>(X, C, out);
    refine2_kernel<<<512, 256>>>(X, C, out);       // 4th launch -> ncu slot
    accum_kernel<<<(N_TOT * 32) / 256, 256>>>(X);
    finalize_kernel<<<(K_CL * D_DIM + 255) / 256, 256>>>(C, out + (size_t)N_TOT * K_CL);
}

// round 11
// speedup vs baseline: 2.2704x; 1.0161x over previous
#include <cuda_runtime.h>
#include <cstdint>
#include <cstddef>

// Problem constants
#define N_TOT 131072   // B*S points
#define D_DIM 256      // feature dim
#define K_CL  512      // clusters

#define MT 128         // points per CTA tile (argmin)
#define TAU 0.2f       // tf32 near-tie threshold (6.5 sigma of 0.03 RMS)
#define MT2 64         // points per CTA tile (refine1)
#define TAU2 1e-3f     // split-tf32 threshold (err < 3e-5 -> >16x margin)

// ---- dynamic SMEM layout for argmin_mma (bytes) ----
#define XSTR 260
#define BSTR 68
#define SM_X   0
#define SM_B0  133120
#define SM_B1  (SM_B0 + 34816)
#define SM_C2  (SM_B1 + 34816)
#define SM_BV  (SM_C2 + 2048)
#define SM_SV  (SM_BV + 2048)
#define SM_IV  (SM_SV + 2048)
#define SMEM_TOTAL (SM_IV + 2048)      // 210944

// ---- dynamic SMEM layout for refine1_mma (bytes) ----
#define BSTR2 36
#define R_XH  0                        // 64 x 260 f32 (hi part)
#define R_XL  66560                    // 64 x 260 f32 (lo part)
#define R_BH0 133120                   // 128 x 36 f32
#define R_BL0 151552
#define R_BH1 169984
#define R_BL1 188416
#define R_C2  206848                   // 512 f32
#define R_PL  208896                   // 64 ints
#define R_BV  209152                   // float[4][64]
#define R_SV  210176
#define R_IV  211200
#define SMEM2_TOTAL 212224

// Scratch (device globals — no allocation allowed)
__device__ int   g_idx[N_TOT];
__device__ float g_sums[K_CL * D_DIM];
__device__ int   g_counts[K_CL];
__device__ float g_c2[K_CL];
__device__ int   g_nref;
__device__ int   g_rlist[N_TOT];
__device__ int   g_nref2;
__device__ int   g_rlist2[N_TOT];

// ---------------- portable PTX helpers (NO 'a'-gated features) -------------
__device__ __forceinline__ uint32_t f2tf(float f) {
    uint32_t r;
    asm("cvt.rna.tf32.f32 %0, %1;" : "=r"(r) : "f"(f));
    return r;
}
__device__ __forceinline__ void mma8(float* d, const uint32_t* a, const uint32_t* b) {
    asm volatile(
        "mma.sync.aligned.m16n8k8.row.col.f32.tf32.tf32.f32 "
        "{%0,%1,%2,%3}, {%4,%5,%6,%7}, {%8,%9}, {%0,%1,%2,%3};"
        : "+f"(d[0]), "+f"(d[1]), "+f"(d[2]), "+f"(d[3])
        : "r"(a[0]), "r"(a[1]), "r"(a[2]), "r"(a[3]), "r"(b[0]), "r"(b[1]));
}

// ---------------------------------------------------------------------------
// init: zero sums/counts/refine counters, c2[k] = sum_d C[k][d]^2 (fp64->fp32)
// ---------------------------------------------------------------------------
__global__ void init_kernel(const float* __restrict__ C) {
    int t = blockIdx.x * blockDim.x + threadIdx.x;
    if (t == 0) { g_nref = 0; g_nref2 = 0; }
    if (t < K_CL * D_DIM) g_sums[t] = 0.0f;
    if (t < K_CL) {
        g_counts[t] = 0;
        const float4* c = (const float4*)(C + (size_t)t * D_DIM);
        double s = 0.0;
        #pragma unroll
        for (int j = 0; j < D_DIM / 4; ++j) {
            float4 v = c[j];
            s += (double)v.x * v.x + (double)v.y * v.y
               + (double)v.z * v.z + (double)v.w * v.w;
        }
        g_c2[t] = (float)s;
    }
}

// ---------------------------------------------------------------------------
// argmin_mma: same CTA tile & traffic as R10 (413us measured), but 512 threads
// (16 warps, 4m x 4n grid of 32x32 warp tiles) -> 4 warps/SMSP latency hiding.
// ---------------------------------------------------------------------------
__global__ __launch_bounds__(512)
void argmin_mma(const float* __restrict__ X, const float* __restrict__ C,
                float* __restrict__ out) {
    extern __shared__ char smem[];
    const int tid  = threadIdx.x;
    const int wid  = tid >> 5, lane = tid & 31;
    const int qrow = lane >> 2, qcol = lane & 3;
    const int wm   = wid & 3,  wn   = wid >> 2;   // 4m x 4n warp grid
    const int RM   = wm * 32,  CN   = wn * 32;
    const int n0   = blockIdx.x * MT;

    float* Xs  = (float*)(smem + SM_X);
    float* Bb[2] = { (float*)(smem + SM_B0), (float*)(smem + SM_B1) };
    float* c2s = (float*)(smem + SM_C2);
    float* bvS = (float*)(smem + SM_BV);
    float* svS = (float*)(smem + SM_SV);
    int*   ivS = (int*)  (smem + SM_IV);

    c2s[tid] = g_c2[tid];   // 512 threads cover all K_CL entries

    float4 pr[4];
    auto ldgB = [&](int q) {
        const int kt = (q >> 2) * 128, db = (q & 3) * 64;
        #pragma unroll
        for (int i = 0; i < 4; ++i) {
            int idx = i * 512 + tid;
            int r = idx >> 4, s = idx & 15;
            pr[i] = *(const float4*)(C + (size_t)(kt + r) * D_DIM + db + s * 4);
        }
    };
    auto stsB = [&](float* B) {
        #pragma unroll
        for (int i = 0; i < 4; ++i) {
            int idx = i * 512 + tid;
            int r = idx >> 4, s = idx & 15;
            float4 w;
            w.x = __uint_as_float(f2tf(pr[i].x));
            w.y = __uint_as_float(f2tf(pr[i].y));
            w.z = __uint_as_float(f2tf(pr[i].z));
            w.w = __uint_as_float(f2tf(pr[i].w));
            *(float4*)(B + r * BSTR + s * 4) = w;
        }
    };

    ldgB(0);
    #pragma unroll
    for (int i = 0; i < 16; ++i) {
        int idx = i * 512 + tid;
        int r = idx >> 6, s = idx & 63;
        float4 v = *(const float4*)(X + (size_t)(n0 + r) * D_DIM + s * 4);
        float4 w;
        w.x = __uint_as_float(f2tf(v.x));
        w.y = __uint_as_float(f2tf(v.y));
        w.z = __uint_as_float(f2tf(v.z));
        w.w = __uint_as_float(f2tf(v.w));
        *(float4*)(Xs + r * XSTR + s * 4) = w;
    }
    stsB(Bb[0]);
    ldgB(1);
    __syncthreads();

    float acc[2][4][4];
    #pragma unroll
    for (int a = 0; a < 2; ++a)
        #pragma unroll
        for (int b = 0; b < 4; ++b)
            #pragma unroll
            for (int c = 0; c < 4; ++c) acc[a][b][c] = 0.0f;

    float best[4], sec[4];
    int   idx4[4];
    #pragma unroll
    for (int t = 0; t < 4; ++t) { best[t] = 3.4e38f; sec[t] = 3.4e38f; idx4[t] = 0; }

    for (int q = 0; q < 16; ++q) {
        const float* Bs = Bb[q & 1];
        const int dbase = (q & 3) * 64;

        #pragma unroll
        for (int ks = 0; ks < 8; ++ks) {
            const int dX = dbase + ks * 8 + qcol;
            uint32_t Af[2][4];
            #pragma unroll
            for (int mt = 0; mt < 2; ++mt) {
                int r = RM + mt * 16 + qrow;
                Af[mt][0] = __float_as_uint(Xs[r * XSTR + dX]);
                Af[mt][1] = __float_as_uint(Xs[(r + 8) * XSTR + dX]);
                Af[mt][2] = __float_as_uint(Xs[r * XSTR + dX + 4]);
                Af[mt][3] = __float_as_uint(Xs[(r + 8) * XSTR + dX + 4]);
            }
            uint32_t Bf[4][2];
            #pragma unroll
            for (int nt = 0; nt < 4; ++nt) {
                int n = CN + nt * 8 + qrow;
                Bf[nt][0] = __float_as_uint(Bs[n * BSTR + ks * 8 + qcol]);
                Bf[nt][1] = __float_as_uint(Bs[n * BSTR + ks * 8 + 4 + qcol]);
            }
            #pragma unroll
            for (int mt = 0; mt < 2; ++mt)
                #pragma unroll
                for (int nt = 0; nt < 4; ++nt)
                    mma8(acc[mt][nt], Af[mt], Bf[nt]);
        }

        if ((q & 3) == 3) {
            const int kt = (q >> 2) * 128;
            #pragma unroll
            for (int mt = 0; mt < 2; ++mt) {
                #pragma unroll
                for (int nt = 0; nt < 4; ++nt) {
                    int k0 = kt + CN + nt * 8 + 2 * qcol;
                    float c20 = c2s[k0], c21 = c2s[k0 + 1];
                    float s0 = fmaf(-2.0f, acc[mt][nt][0], c20);
                    float s1 = fmaf(-2.0f, acc[mt][nt][1], c21);
                    float s2 = fmaf(-2.0f, acc[mt][nt][2], c20);
                    float s3 = fmaf(-2.0f, acc[mt][nt][3], c21);
                    int t0 = mt * 2, t1 = mt * 2 + 1;
                    if (s0 < sec[t0]) { if (s0 < best[t0]) { sec[t0] = best[t0]; best[t0] = s0; idx4[t0] = k0; } else sec[t0] = s0; }
                    if (s1 < sec[t0]) { if (s1 < best[t0]) { sec[t0] = best[t0]; best[t0] = s1; idx4[t0] = k0 + 1; } else sec[t0] = s1; }
                    if (s2 < sec[t1]) { if (s2 < best[t1]) { sec[t1] = best[t1]; best[t1] = s2; idx4[t1] = k0; } else sec[t1] = s2; }
                    if (s3 < sec[t1]) { if (s3 < best[t1]) { sec[t1] = best[t1]; best[t1] = s3; idx4[t1] = k0 + 1; } else sec[t1] = s3; }
                    acc[mt][nt][0] = 0.0f; acc[mt][nt][1] = 0.0f;
                    acc[mt][nt][2] = 0.0f; acc[mt][nt][3] = 0.0f;
                }
            }
        }

        __syncthreads();
        if (q + 1 < 16) stsB(Bb[(q + 1) & 1]);
        if (q + 2 < 16) ldgB(q + 2);
        if (q + 1 < 16) __syncthreads();
    }

    // quad merge (lanes differing in qcol share rows)
    #pragma unroll
    for (int t = 0; t < 4; ++t) {
        float b = best[t], s = sec[t];
        int   i = idx4[t];
        #pragma unroll
        for (int o = 1; o <= 2; o <<= 1) {
            float b2 = __shfl_xor_sync(0xFFFFFFFFu, b, o);
            float s2 = __shfl_xor_sync(0xFFFFFFFFu, s, o);
            int   i2 = __shfl_xor_sync(0xFFFFFFFFu, i, o);
            if (b2 < b || (b2 == b && i2 < i)) { s = fminf(b, s2); b = b2; i = i2; }
            else                               { s = fminf(s, b2); }
        }
        if (qcol == 0) {
            int row = RM + (t >> 1) * 16 + qrow + (t & 1) * 8;   // unique per wn
            bvS[wn * 128 + row] = b;
            svS[wn * 128 + row] = s;
            ivS[wn * 128 + row] = i;
        }
    }
    __syncthreads();

    // final cross-warp-column merge + decision (one thread per point)
    if (tid < 128) {
        float bb = bvS[tid], ss = svS[tid];
        int   ii = ivS[tid];
        #pragma unroll
        for (int w = 1; w < 4; ++w) {
            float b2 = bvS[w * 128 + tid], s2 = svS[w * 128 + tid];
            int   i2 = ivS[w * 128 + tid];
            if (b2 < bb || (b2 == bb && i2 < ii)) { ss = fminf(bb, s2); bb = b2; ii = i2; }
            else                                   { ss = fminf(ss, b2); }
        }
        int n = n0 + tid;
        g_idx[n] = ii;
        int mark = ii;
        if (ss - bb < TAU) {
            int slot = atomicAdd(&g_nref, 1);
            g_rlist[slot] = n;
            mark = -1;                      // tiered refine writes the 1.0 later
        }
        ivS[tid] = mark;
    }
    __syncthreads();

    // stream full one-hot rows (replaces global memset)
    #pragma unroll
    for (int i = 0; i < 32; ++i) {
        int idx = i * 512 + tid;
        int row = idx >> 7, s = idx & 127;
        int m = ivS[row];
        float4 v = make_float4(0.f, 0.f, 0.f, 0.f);
        if ((m >> 2) == s) ((float*)&v)[m & 3] = 1.0f;
        __stcs((float4*)(out + (size_t)(n0 + row) * K_CL + s * 4), v);
    }
}

// ---------------------------------------------------------------------------
// refine1: split-tf32 (3-pass) MMA re-score of near-tie points (measured 79us).
// ---------------------------------------------------------------------------
__global__ __launch_bounds__(256)
void refine1_mma(const float* __restrict__ X, const float* __restrict__ C,
                 float* __restrict__ out) {
    const int nref  = g_nref;
    const int tile0 = blockIdx.x * MT2;
    if (tile0 >= nref) return;

    extern __shared__ char smem[];
    const int tid  = threadIdx.x;
    const int wid  = tid >> 5, lane = tid & 31;
    const int qrow = lane >> 2, qcol = lane & 3;
    const int wm   = wid & 1,  wn   = wid >> 1;
    const int RM   = wm * 32,  CN   = wn * 32;

    float* Xh  = (float*)(smem + R_XH);
    float* Xl  = (float*)(smem + R_XL);
    float* Bh[2] = { (float*)(smem + R_BH0), (float*)(smem + R_BH1) };
    float* Bl[2] = { (float*)(smem + R_BL0), (float*)(smem + R_BL1) };
    float* c2s = (float*)(smem + R_C2);
    int*   plist = (int*)(smem + R_PL);
    float* bvS = (float*)(smem + R_BV);
    float* svS = (float*)(smem + R_SV);
    int*   ivS = (int*)  (smem + R_IV);

    c2s[tid]       = g_c2[tid];
    c2s[tid + 256] = g_c2[tid + 256];
    if (tid < MT2) {
        int idx = tile0 + tid;
        plist[tid] = g_rlist[idx < nref ? idx : nref - 1];
    }
    __syncthreads();

    float4 pr[4];
    auto ldgB = [&](int q) {
        const int kt = (q >> 3) * 128, db = (q & 7) * 32;
        #pragma unroll
        for (int i = 0; i < 4; ++i) {
            int idx = i * 256 + tid;
            int r = idx >> 3, s = idx & 7;
            pr[i] = *(const float4*)(C + (size_t)(kt + r) * D_DIM + db + s * 4);
        }
    };
    auto stsB = [&](float* BH, float* BL) {
        #pragma unroll
        for (int i = 0; i < 4; ++i) {
            int idx = i * 256 + tid;
            int r = idx >> 3, s = idx & 7;
            float4 h, l;
            h.x = __uint_as_float(f2tf(pr[i].x)); l.x = __uint_as_float(f2tf(pr[i].x - h.x));
            h.y = __uint_as_float(f2tf(pr[i].y)); l.y = __uint_as_float(f2tf(pr[i].y - h.y));
            h.z = __uint_as_float(f2tf(pr[i].z)); l.z = __uint_as_float(f2tf(pr[i].z - h.z));
            h.w = __uint_as_float(f2tf(pr[i].w)); l.w = __uint_as_float(f2tf(pr[i].w - h.w));
            *(float4*)(BH + r * BSTR2 + s * 4) = h;
            *(float4*)(BL + r * BSTR2 + s * 4) = l;
        }
    };

    ldgB(0);
    #pragma unroll
    for (int i = 0; i < 16; ++i) {
        int idx = i * 256 + tid;
        int r = idx >> 6, s = idx & 63;
        float4 v = *(const float4*)(X + (size_t)plist[r] * D_DIM + s * 4);
        float4 h, l;
        h.x = __uint_as_float(f2tf(v.x)); l.x = __uint_as_float(f2tf(v.x - h.x));
        h.y = __uint_as_float(f2tf(v.y)); l.y = __uint_as_float(f2tf(v.y - h.y));
        h.z = __uint_as_float(f2tf(v.z)); l.z = __uint_as_float(f2tf(v.z - h.z));
        h.w = __uint_as_float(f2tf(v.w)); l.w = __uint_as_float(f2tf(v.w - h.w));
        *(float4*)(Xh + r * XSTR + s * 4) = h;
        *(float4*)(Xl + r * XSTR + s * 4) = l;
    }
    stsB(Bh[0], Bl[0]);
    ldgB(1);
    __syncthreads();

    float acc[2][4][4];
    #pragma unroll
    for (int a = 0; a < 2; ++a)
        #pragma unroll
        for (int b = 0; b < 4; ++b)
            #pragma unroll
            for (int c = 0; c < 4; ++c) acc[a][b][c] = 0.0f;

    float best[4], sec[4];
    int   idx4[4];
    #pragma unroll
    for (int t = 0; t < 4; ++t) { best[t] = 3.4e38f; sec[t] = 3.4e38f; idx4[t] = 0; }

    for (int q = 0; q < 32; ++q) {
        const int sbuf = q & 1;
        const int dc   = q & 7;
        const float* BsH = Bh[sbuf];
        const float* BsL = Bl[sbuf];

        #pragma unroll
        for (int ks = 0; ks < 4; ++ks) {
            const int dX = dc * 32 + ks * 8 + qcol;
            uint32_t Ah[2][4], Al[2][4];
            #pragma unroll
            for (int mt = 0; mt < 2; ++mt) {
                int r = RM + mt * 16 + qrow;
                Ah[mt][0] = __float_as_uint(Xh[r * XSTR + dX]);
                Ah[mt][1] = __float_as_uint(Xh[(r + 8) * XSTR + dX]);
                Ah[mt][2] = __float_as_uint(Xh[r * XSTR + dX + 4]);
                Ah[mt][3] = __float_as_uint(Xh[(r + 8) * XSTR + dX + 4]);
                Al[mt][0] = __float_as_uint(Xl[r * XSTR + dX]);
                Al[mt][1] = __float_as_uint(Xl[(r + 8) * XSTR + dX]);
                Al[mt][2] = __float_as_uint(Xl[r * XSTR + dX + 4]);
                Al[mt][3] = __float_as_uint(Xl[(r + 8) * XSTR + dX + 4]);
            }
            uint32_t BhF[4][2], BlF[4][2];
            #pragma unroll
            for (int nt = 0; nt < 4; ++nt) {
                int n = CN + nt * 8 + qrow;
                BhF[nt][0] = __float_as_uint(BsH[n * BSTR2 + ks * 8 + qcol]);
                BhF[nt][1] = __float_as_uint(BsH[n * BSTR2 + ks * 8 + 4 + qcol]);
                BlF[nt][0] = __float_as_uint(BsL[n * BSTR2 + ks * 8 + qcol]);
                BlF[nt][1] = __float_as_uint(BsL[n * BSTR2 + ks * 8 + 4 + qcol]);
            }
            #pragma unroll
            for (int mt = 0; mt < 2; ++mt)
                #pragma unroll
                for (int nt = 0; nt < 4; ++nt) {
                    mma8(acc[mt][nt], Ah[mt], BhF[nt]);
                    mma8(acc[mt][nt], Ah[mt], BlF[nt]);
                    mma8(acc[mt][nt], Al[mt], BhF[nt]);
                }
        }

        if (dc == 7) {
            const int kt = (q >> 3) * 128;
            #pragma unroll
            for (int mt = 0; mt < 2; ++mt) {
                #pragma unroll
                for (int nt = 0; nt < 4; ++nt) {
                    int k0 = kt + CN + nt * 8 + 2 * qcol;
                    float c20 = c2s[k0], c21 = c2s[k0 + 1];
                    float s0 = fmaf(-2.0f, acc[mt][nt][0], c20);
                    float s1 = fmaf(-2.0f, acc[mt][nt][1], c21);
                    float s2 = fmaf(-2.0f, acc[mt][nt][2], c20);
                    float s3 = fmaf(-2.0f, acc[mt][nt][3], c21);
                    int t0 = mt * 2, t1 = mt * 2 + 1;
                    if (s0 < sec[t0]) { if (s0 < best[t0]) { sec[t0] = best[t0]; best[t0] = s0; idx4[t0] = k0; } else sec[t0] = s0; }
                    if (s1 < sec[t0]) { if (s1 < best[t0]) { sec[t0] = best[t0]; best[t0] = s1; idx4[t0] = k0 + 1; } else sec[t0] = s1; }
                    if (s2 < sec[t1]) { if (s2 < best[t1]) { sec[t1] = best[t1]; best[t1] = s2; idx4[t1] = k0; } else sec[t1] = s2; }
                    if (s3 < sec[t1]) { if (s3 < best[t1]) { sec[t1] = best[t1]; best[t1] = s3; idx4[t1] = k0 + 1; } else sec[t1] = s3; }
                    acc[mt][nt][0] = 0.0f; acc[mt][nt][1] = 0.0f;
                    acc[mt][nt][2] = 0.0f; acc[mt][nt][3] = 0.0f;
                }
            }
        }

        __syncthreads();
        if (q + 1 < 32) stsB(Bh[(q + 1) & 1], Bl[(q + 1) & 1]);
        if (q + 2 < 32) ldgB(q + 2);
        if (q + 1 < 32) __syncthreads();
    }

    #pragma unroll
    for (int t = 0; t < 4; ++t) {
        float b = best[t], s = sec[t];
        int   i = idx4[t];
        #pragma unroll
        for (int o = 1; o <= 2; o <<= 1) {
            float b2 = __shfl_xor_sync(0xFFFFFFFFu, b, o);
            float s2 = __shfl_xor_sync(0xFFFFFFFFu, s, o);
            int   i2 = __shfl_xor_sync(0xFFFFFFFFu, i, o);
            if (b2 < b || (b2 == b && i2 < i)) { s = fminf(b, s2); b = b2; i = i2; }
            else                               { s = fminf(s, b2); }
        }
        if (qcol == 0) {
            int row = RM + (t >> 1) * 16 + qrow + (t & 1) * 8;
            bvS[wn * 64 + row] = b;
            svS[wn * 64 + row] = s;
            ivS[wn * 64 + row] = i;
        }
    }
    __syncthreads();

    if (tid < MT2) {
        float bb = bvS[tid], ss = svS[tid];
        int   ii = ivS[tid];
        #pragma unroll
        for (int w = 1; w < 4; ++w) {
            float b2 = bvS[w * 64 + tid], s2 = svS[w * 64 + tid];
            int   i2 = ivS[w * 64 + tid];
            if (b2 < bb || (b2 == bb && i2 < ii)) { ss = fminf(bb, s2); bb = b2; ii = i2; }
            else                                   { ss = fminf(ss, b2); }
        }
        int idx = tile0 + tid;
        if (idx < nref) {
            int n = plist[tid];
            if (ss - bb >= TAU2) {
                g_idx[n] = ii;
                out[(size_t)n * K_CL + ii] = 1.0f;   // row already all-zero
            } else {
                int slot = atomicAdd(&g_nref2, 1);
                g_rlist2[slot] = n;                  // exact tier-2 decides
            }
        }
    }
}

// ---------------------------------------------------------------------------
// refine2 (exact tier): Kahan fp32 dots, reference rounding order. (35us meas.)
// ---------------------------------------------------------------------------
__device__ __forceinline__ void kadd(float& s, float& comp, float t) {
    float y = __fsub_rn(t, comp);
    float u = __fadd_rn(s, y);
    comp = __fsub_rn(__fsub_rn(u, s), y);
    s = u;
}

__global__ __launch_bounds__(256)
void refine2_kernel(const float* __restrict__ X, const float* __restrict__ C,
                    float* __restrict__ out) {
    __shared__ float  xsh[D_DIM];
    __shared__ double xwr[8];
    __shared__ float  x2sh;
    __shared__ float  rv[256];
    __shared__ int    ri[256];

    const int tid  = threadIdx.x;
    const int nref = g_nref2;

    for (int it = blockIdx.x; it < nref; it += gridDim.x) {
        const int n = g_rlist2[it];
        __syncthreads();
        xsh[tid] = X[(size_t)n * D_DIM + tid];
        __syncthreads();
        {
            double p = (double)xsh[tid] * (double)xsh[tid];
            #pragma unroll
            for (int o = 16; o >= 1; o >>= 1)
                p += __shfl_xor_sync(0xFFFFFFFFu, p, o);
            if ((tid & 31) == 0) xwr[tid >> 5] = p;
            __syncthreads();
            if (tid == 0) {
                double t = 0.0;
                #pragma unroll
                for (int w = 0; w < 8; ++w) t += xwr[w];
                x2sh = (float)t;
            }
            __syncthreads();
        }
        const float x2f = x2sh;
        const float4* xs4 = (const float4*)xsh;

        float bv = 3.4e38f;
        int   bi = 0x7fffffff;
        #pragma unroll
        for (int kk = 0; kk < 2; ++kk) {
            const int k = 2 * tid + kk;
            const float4* cp = (const float4*)(C + (size_t)k * D_DIM);
            float s = 0.0f, comp = 0.0f;
            #pragma unroll 4
            for (int j = 0; j < D_DIM / 4; ++j) {
                float4 cv = cp[j];
                float4 xv = xs4[j];
                kadd(s, comp, __fmul_rn(cv.x, xv.x));
                kadd(s, comp, __fmul_rn(cv.y, xv.y));
                kadd(s, comp, __fmul_rn(cv.z, xv.z));
                kadd(s, comp, __fmul_rn(cv.w, xv.w));
            }
            float dotf = __fadd_rn(s, comp);
            float m = __fmul_rn(2.0f, dotf);
            float a = __fsub_rn(x2f, m);
            float dist = __fadd_rn(a, g_c2[k]);
            if (dist < bv || (dist == bv && k < bi)) { bv = dist; bi = k; }
        }
        rv[tid] = bv; ri[tid] = bi;
        __syncthreads();
        #pragma unroll
        for (int st = 128; st > 0; st >>= 1) {
            if (tid < st) {
                float ov = rv[tid + st]; int oi = ri[tid + st];
                if (ov < rv[tid] || (ov == rv[tid] && oi < ri[tid])) {
                    rv[tid] = ov; ri[tid] = oi;
                }
            }
            __syncthreads();
        }
        if (tid == 0) {
            g_idx[n] = ri[0];
            out[(size_t)n * K_CL + ri[0]] = 1.0f;
        }
    }
}

// ---------------------------------------------------------------------------
// scatter-reduce into per-cluster sums + counts (one warp per point).
// Vectorized: red.global.add.v4.f32 (sm_90+) -> 4x fewer reduction messages.
// ---------------------------------------------------------------------------
__global__ void accum_kernel(const float* __restrict__ X) {
    int gw   = (blockIdx.x * blockDim.x + threadIdx.x) >> 5;
    int lane = threadIdx.x & 31;
    if (gw >= N_TOT) return;
    int k = g_idx[gw];
    const float4* x = (const float4*)(X + (size_t)gw * D_DIM);
    float* s = g_sums + (size_t)k * D_DIM;
    #pragma unroll
    for (int j = 0; j < 2; ++j) {
        float4 v = x[lane + j * 32];
        float* p = s + (lane + j * 32) * 4;
        asm volatile("red.global.add.v4.f32 [%0], {%1, %2, %3, %4};"
                     :: "l"(p), "f"(v.x), "f"(v.y), "f"(v.z), "f"(v.w)
                     : "memory");
    }
    if (lane == 0) atomicAdd(&g_counts[k], 1);
}

// ---------------------------------------------------------------------------
__global__ void finalize_kernel(const float* __restrict__ C, float* __restrict__ outc) {
    int t = blockIdx.x * blockDim.x + threadIdx.x;
    if (t >= K_CL * D_DIM) return;
    int k = t >> 8;
    float cnt = (float)g_counts[k];
    float nc  = g_sums[t] / cnt;
    outc[t] = fmaf(0.9f, C[t], 0.1f * nc);
}

// ---------------------------------------------------------------------------
extern "C" void kernel_launch(void* const* d_in, const int* in_sizes, int n_in,
                              void* d_out, int out_size) {
    const float* X = (const float*)d_in[0];
    const float* C = (const float*)d_in[1];
    float* out = (float*)d_out;
    (void)in_sizes; (void)n_in; (void)out_size;

    cudaFuncSetAttribute(argmin_mma, cudaFuncAttributeMaxDynamicSharedMemorySize,
                         SMEM_TOTAL);
    cudaFuncSetAttribute(refine1_mma, cudaFuncAttributeMaxDynamicSharedMemorySize,
                         SMEM2_TOTAL);

    init_kernel<<<(K_CL * D_DIM + 255) / 256, 256>>>(C);
    argmin_mma<<<N_TOT / MT, 512, SMEM_TOTAL>>>(X, C, out);
    refine1_mma<<<N_TOT / MT2, 256, SMEM2_TOTAL>>>(X, C, out);
    refine2_kernel<<<512, 256>>>(X, C, out);       // 4th launch -> ncu slot
    accum_kernel<<<(N_TOT * 32) / 256, 256>>>(X);
    finalize_kernel<<<(K_CL * D_DIM + 255) / 256, 256>>>(C, out + (size_t)N_TOT * K_CL);
}